// round 9
// baseline (speedup 1.0000x reference)
#include <cuda_runtime.h>
#include <string.h>

// ---------------- problem constants ----------------
#define B_      8
#define N_      8192
#define C_      64
#define NPOINT  2048
#define NSAMPLE 32
#define ROWS_TOTAL (B_*NPOINT*NSAMPLE)   // 524288
#define NGROUP   (B_*NPOINT)             // 16384

// ---------------- device scratch (no cudaMalloc allowed) ----------------
__device__ int   d_ball[ROWS_TOTAL];
// transposed intermediates: [channel][row]
__device__ float d_out1T[(size_t)64*ROWS_TOTAL];
__device__ float d_out2T[(size_t)64*ROWS_TOTAL];
__device__ float d_gmax[(size_t)NGROUP*128];
__device__ float d_gmin[(size_t)NGROUP*128];

__device__ float g_sum1[64],  g_sq1[64];
__device__ float g_sum2[64],  g_sq2[64];
__device__ float g_sum3[128], g_sq3[128];
__device__ float g_scale1[64],  g_shift1[64];
__device__ float g_scale2[64],  g_shift2[64];
__device__ float g_scale3[128], g_shift3[128];

// ---------------- packed f32x2 helpers ----------------
__device__ __forceinline__ float2 ffma2(float2 a, float2 b, float2 c) {
    unsigned long long ua, ub, uc;
    memcpy(&ua, &a, 8); memcpy(&ub, &b, 8); memcpy(&uc, &c, 8);
    asm("fma.rn.f32x2 %0, %1, %2, %0;" : "+l"(uc) : "l"(ua), "l"(ub));
    float2 d; memcpy(&d, &uc, 8); return d;
}
__device__ __forceinline__ float2 fadd2(float2 a, float2 b) {
    unsigned long long ua, ub, uc;
    memcpy(&ua, &a, 8); memcpy(&ub, &b, 8);
    asm("add.rn.f32x2 %0, %1, %2;" : "=l"(uc) : "l"(ua), "l"(ub));
    float2 d; memcpy(&d, &uc, 8); return d;
}
__device__ __forceinline__ float2 fmul2(float2 a, float2 b) {
    unsigned long long ua, ub, uc;
    memcpy(&ua, &a, 8); memcpy(&ub, &b, 8);
    asm("mul.rn.f32x2 %0, %1, %2;" : "=l"(uc) : "l"(ua), "l"(ub));
    float2 d; memcpy(&d, &uc, 8); return d;
}

// warp-wide redux (sm_80+)
__device__ __forceinline__ unsigned redux_max_u32(unsigned v) {
    unsigned d; asm("redux.sync.max.u32 %0, %1, 0xffffffff;" : "=r"(d) : "r"(v)); return d;
}
__device__ __forceinline__ unsigned redux_min_u32(unsigned v) {
    unsigned d; asm("redux.sync.min.u32 %0, %1, 0xffffffff;" : "=r"(d) : "r"(v)); return d;
}

// order-preserving float<->uint for atomicMax/Min on signed floats
__device__ __forceinline__ unsigned enc_f(float f) {
    unsigned u = __float_as_uint(f);
    return (u & 0x80000000u) ? ~u : (u | 0x80000000u);
}
__device__ __forceinline__ float dec_f(unsigned u) {
    unsigned v = (u & 0x80000000u) ? (u & 0x7FFFFFFFu) : ~u;
    return __uint_as_float(v);
}
#define ENC_NEG_INF 0x007FFFFFu
#define ENC_POS_INF 0xFF800000u

// exact (non-FMA) squared distance, matching XLA f32: (dx*dx + dy*dy) + dz*dz
__device__ __forceinline__ float d2_exact(float dx, float dy, float dz) {
    return __fadd_rn(__fadd_rn(__fmul_rn(dx,dx), __fmul_rn(dy,dy)), __fmul_rn(dz,dz));
}

// ---------------- kernel 0: zero stats ----------------
__global__ void zero_stats() {
    int t = threadIdx.x;
    if (t < 64) { g_sum1[t]=0.f; g_sq1[t]=0.f; g_sum2[t]=0.f; g_sq2[t]=0.f; }
    if (t < 128){ g_sum3[t]=0.f; g_sq3[t]=0.f; }
}

// ---------------- kernel 1: furthest point sampling (r8, unchanged) ----------------
#define FPS_SMEM (3*N_*4 + NPOINT*4 + 2*64*4)
__global__ __launch_bounds__(1024, 1) void fps_kernel(const float* __restrict__ xyz,
                                                      float* __restrict__ newxyz) {
    extern __shared__ float sm[];
    float* xs = sm;
    float* ys = sm + N_;
    float* zs = sm + 2*N_;
    int*   picks = (int*)(sm + 3*N_);
    unsigned* sval = (unsigned*)(picks + NPOINT);  // [2][32]
    unsigned* sidx = sval + 64;                    // [2][32]

    const int b = blockIdx.x, tid = threadIdx.x;
    const int lane = tid & 31, wid = tid >> 5;
    const float* xb = xyz + (size_t)b * N_ * 3;

    for (int j = tid; j < 3*N_; j += 1024) {
        float v = xb[j];
        int p = j / 3, c = j - p*3;
        ((c == 0) ? xs : (c == 1) ? ys : zs)[p] = v;
    }
    if (tid == 0) picks[0] = 0;
    __syncthreads();

    float2 RX[4], RY[4], RZ[4];
    unsigned Du[8];
#pragma unroll
    for (int j = 0; j < 4; j++) {
        int p0 = tid + (2*j)*1024, p1 = p0 + 1024;
        RX[j] = make_float2(xs[p0], xs[p1]);
        RY[j] = make_float2(ys[p0], ys[p1]);
        RZ[j] = make_float2(zs[p0], zs[p1]);
        Du[2*j]   = __float_as_uint(1e10f);
        Du[2*j+1] = __float_as_uint(1e10f);
    }

    int last = 0;
    for (int it = 1; it < NPOINT; ++it) {
        float px = xs[last], py = ys[last], pz = zs[last];
        float2 nx2 = make_float2(-px, -px);
        float2 ny2 = make_float2(-py, -py);
        float2 nz2 = make_float2(-pz, -pz);

#pragma unroll
        for (int j = 0; j < 4; j++) {
            float2 dx = fadd2(RX[j], nx2);
            float2 dy = fadd2(RY[j], ny2);
            float2 dz = fadd2(RZ[j], nz2);
            float2 s  = fadd2(fadd2(fmul2(dx,dx), fmul2(dy,dy)), fmul2(dz,dz));
            Du[2*j]   = umin(Du[2*j],   __float_as_uint(s.x));
            Du[2*j+1] = umin(Du[2*j+1], __float_as_uint(s.y));
        }
        unsigned m01 = umax(Du[0], Du[1]), m23 = umax(Du[2], Du[3]);
        unsigned m45 = umax(Du[4], Du[5]), m67 = umax(Du[6], Du[7]);
        unsigned bv  = umax(umax(m01, m23), umax(m45, m67));

        unsigned wmax = redux_max_u32(bv);
        const int buf = (it & 1) << 5;
        if (lane == 0) sval[buf + wid] = wmax;
        __syncthreads();
        unsigned gm = redux_max_u32(sval[buf + lane]);   // global max value

        unsigned idxv = 0xFFFFFFFFu;
        if (wmax == gm) {                 // warp-uniform
            unsigned cand = 0xFFFFFFFFu;
            if (bv == gm) {
#pragma unroll
                for (int s = 7; s >= 0; --s)
                    if (Du[s] == gm) cand = (unsigned)(tid + (s << 10));
            }
            idxv = redux_min_u32(cand);
        }
        if (lane == 0) sidx[buf + wid] = idxv;
        __syncthreads();
        last = (int)redux_min_u32(sidx[buf + lane]);
        if (tid == 0) picks[it] = last;
    }
    __syncthreads();
    for (int s = tid; s < NPOINT; s += 1024) {
        int j = picks[s];
        float* o = newxyz + (size_t)(b*NPOINT + s)*3;
        o[0] = xs[j]; o[1] = ys[j]; o[2] = zs[j];
    }
}

// ---------------- kernel 2: ball query (warp-autonomous, unchanged) ----------------
__global__ __launch_bounds__(256) void ball_kernel(const float* __restrict__ xyz,
                                                   const float* __restrict__ nxyz) {
    __shared__ int sidx[8][32];
    const int lane = threadIdx.x & 31, w = threadIdx.x >> 5;
    const int g = blockIdx.x * 8 + w;           // global query id
    const int b = g >> 11;                      // 2048 queries per batch
    const float* qp = nxyz + (size_t)g * 3;
    const float qx = qp[0], qy = qp[1], qz = qp[2];
    const float R2f = (float)(0.4 * 0.4);
    const float* xb = xyz + (size_t)b * N_ * 3;

    int cnt = 0;
    for (int t0 = 0; t0 < N_; t0 += 32) {
        const int p = t0 + lane;
        const float* pp = xb + (size_t)p * 3;
        float x = __ldg(pp), y = __ldg(pp + 1), z = __ldg(pp + 2);
        float d2 = d2_exact(qx - x, qy - y, qz - z);
        bool ok = d2 < R2f;
        unsigned m = __ballot_sync(0xffffffffu, ok);
        if (m) {
            int pos = cnt + __popc(m & ((1u << lane) - 1u));
            if (ok && pos < 32) sidx[w][pos] = p;
            cnt += __popc(m);
            if (cnt >= 32) break;
        }
    }
    __syncwarp();
    int v = 0;
    if (cnt) {
        int first = sidx[w][0];
        v = (lane < cnt) ? sidx[w][lane] : first;
    }
    d_ball[((size_t)g << 5) + lane] = v;
}

// ================= GEMM micro-kernels =================
// gemm1/2: 256 threads, 128-row x 64-col tile, 4 rows x 8 cols per thread
// (tr = tid>>3 in [0,32), tc = tid&7). Per k: 1 LDS.128 A + 2 LDS.128 B feeding
// 16 FFMA2. smem 52.5/50 KB -> 4 blocks/SM -> 32 warps (r3-level occupancy).

// ---------------- GEMM 1: feats(gathered 67) @ W1 -> out1T + stats ----------------
#define G1_SMEM ((67*132 + 67*64)*4)
__global__ __launch_bounds__(256, 4) void gemm1_kernel(const float* __restrict__ xyz,
                                                       const float* __restrict__ points,
                                                       const float* __restrict__ W1,
                                                       const float* __restrict__ nxyz) {
    extern __shared__ float sm[];
    float* As = sm;             // [67][132] k-major
    float* Bs = sm + 67*132;    // [67][64]
    __shared__ float ssum[64], ssq[64];

    const int tid = threadIdx.x;
    const int R0 = blockIdx.x * 128;
    if (tid < 64) { ssum[tid] = 0.f; ssq[tid] = 0.f; }
    for (int i = tid; i < 67*64; i += 256) Bs[i] = W1[i];

    const int wid = tid >> 5, lane = tid & 31;
    for (int rr = wid; rr < 128; rr += 8) {
        int row = R0 + rr;
        int b = row >> 16, rem = row & 65535, s = rem >> 5;
        int j = d_ball[row];
        const float* prow = points + ((size_t)(b*N_ + j)) * 64;
        As[(3 + lane)*132 + rr]  = prow[lane];
        As[(35 + lane)*132 + rr] = prow[lane + 32];
        if (lane < 3)
            As[lane*132 + rr] = xyz[(size_t)(b*N_ + j)*3 + lane]
                              - nxyz[(size_t)(b*NPOINT + s)*3 + lane];
    }
    __syncthreads();

    const int tc = tid & 7, tr = tid >> 3;   // tr in [0,32): rows tr*4..+3
    float2 acc[2][8];   // [rowpair][col]
#pragma unroll
    for (int r = 0; r < 2; r++)
#pragma unroll
        for (int c = 0; c < 8; c++) acc[r][c] = make_float2(0.f, 0.f);

    for (int kk = 0; kk < 67; ++kk) {
        float4 a = *(const float4*)(As + kk*132 + tr*4);
        float2 ap[2] = { make_float2(a.x, a.y), make_float2(a.z, a.w) };
        float4 b0 = *(const float4*)(Bs + kk*64 + tc*8);
        float4 b1 = *(const float4*)(Bs + kk*64 + tc*8 + 4);
        float2 bb[8] = { make_float2(b0.x,b0.x), make_float2(b0.y,b0.y),
                         make_float2(b0.z,b0.z), make_float2(b0.w,b0.w),
                         make_float2(b1.x,b1.x), make_float2(b1.y,b1.y),
                         make_float2(b1.z,b1.z), make_float2(b1.w,b1.w) };
#pragma unroll
        for (int r = 0; r < 2; r++)
#pragma unroll
            for (int c = 0; c < 8; c++)
                acc[r][c] = ffma2(ap[r], bb[c], acc[r][c]);
    }

    // epilogue: transposed store (column-major) + stats
#pragma unroll
    for (int c = 0; c < 8; c++) {
        int col = tc*8 + c;
        float4 v = make_float4(acc[0][c].x, acc[0][c].y, acc[1][c].x, acc[1][c].y);
        *(float4*)(d_out1T + (size_t)col*ROWS_TOTAL + R0 + tr*4) = v;
        float su = v.x+v.y+v.z+v.w;
        float sq = v.x*v.x+v.y*v.y+v.z*v.z+v.w*v.w;
        atomicAdd(&ssum[col], su);
        atomicAdd(&ssq [col], sq);
    }
    __syncthreads();
    if (tid < 64) { atomicAdd(&g_sum1[tid], ssum[tid]); atomicAdd(&g_sq1[tid], ssq[tid]); }
}

// ---------------- GEMM 2: relu(bn1(out1T)) @ W2 -> out2T + stats ----------------
#define G2_SMEM ((64*132 + 64*64)*4)
__global__ __launch_bounds__(256, 4) void gemm2_kernel(const float* __restrict__ W2) {
    extern __shared__ float sm[];
    float* As = sm;             // [64][132]
    float* Bs = sm + 64*132;    // [64][64]
    __shared__ float ssum[64], ssq[64];

    const int tid = threadIdx.x;
    const int R0 = blockIdx.x * 128;
    if (tid < 64) { ssum[tid] = 0.f; ssq[tid] = 0.f; }
    for (int i = tid; i < 64*64; i += 256) Bs[i] = W2[i];

    const int wid = tid >> 5, lane = tid & 31;
    // gather: warps 0-3 rows 0-127 / c 0-31, warps 4-7 same rows / c 32-63
    {
        const int rbase = (wid & 3)*32 + lane;       // 0..127
        const int c0 = (wid >> 2)*32;
        const float* src = d_out1T + R0 + rbase;
#pragma unroll 4
        for (int cc = 0; cc < 32; cc++) {
            int c = c0 + cc;
            float v = __ldg(src + (size_t)c*ROWS_TOTAL);
            As[c*132 + rbase] = fmaxf(0.f, fmaf(v, __ldg(&g_scale1[c]), __ldg(&g_shift1[c])));
        }
    }
    __syncthreads();

    const int tc = tid & 7, tr = tid >> 3;
    float2 acc[2][8];
#pragma unroll
    for (int r = 0; r < 2; r++)
#pragma unroll
        for (int c = 0; c < 8; c++) acc[r][c] = make_float2(0.f, 0.f);

    for (int kk = 0; kk < 64; ++kk) {
        float4 a = *(const float4*)(As + kk*132 + tr*4);
        float2 ap[2] = { make_float2(a.x, a.y), make_float2(a.z, a.w) };
        float4 b0 = *(const float4*)(Bs + kk*64 + tc*8);
        float4 b1 = *(const float4*)(Bs + kk*64 + tc*8 + 4);
        float2 bb[8] = { make_float2(b0.x,b0.x), make_float2(b0.y,b0.y),
                         make_float2(b0.z,b0.z), make_float2(b0.w,b0.w),
                         make_float2(b1.x,b1.x), make_float2(b1.y,b1.y),
                         make_float2(b1.z,b1.z), make_float2(b1.w,b1.w) };
#pragma unroll
        for (int r = 0; r < 2; r++)
#pragma unroll
            for (int c = 0; c < 8; c++)
                acc[r][c] = ffma2(ap[r], bb[c], acc[r][c]);
    }

#pragma unroll
    for (int c = 0; c < 8; c++) {
        int col = tc*8 + c;
        float4 v = make_float4(acc[0][c].x, acc[0][c].y, acc[1][c].x, acc[1][c].y);
        *(float4*)(d_out2T + (size_t)col*ROWS_TOTAL + R0 + tr*4) = v;
        float su = v.x+v.y+v.z+v.w;
        float sq = v.x*v.x+v.y*v.y+v.z*v.z+v.w*v.w;
        atomicAdd(&ssum[col], su);
        atomicAdd(&ssq [col], sq);
    }
    __syncthreads();
    if (tid < 64) { atomicAdd(&g_sum2[tid], ssum[tid]); atomicAdd(&g_sq2[tid], ssq[tid]); }
}

// ---------------- GEMM 3: relu(bn2(out2T)) @ W3 -> group max/min + stats ----------------
#define G3_SMEM ((64*132 + 64*128)*4)
__global__ __launch_bounds__(256) void gemm3_kernel(const float* __restrict__ W3) {
    extern __shared__ float sm[];
    float* As = sm;            // [64][132] k-major
    float* Bs = sm + 64*132;   // [64][128]
    __shared__ unsigned smax[512], smin[512];
    __shared__ float ssum[128], ssq[128];

    const int tid = threadIdx.x;
    const int R0 = blockIdx.x * 128;
    for (int i = tid; i < 512; i += 256) { smax[i] = ENC_NEG_INF; smin[i] = ENC_POS_INF; }
    if (tid < 128) { ssum[tid] = 0.f; ssq[tid] = 0.f; }
    for (int i = tid; i < 64*128; i += 256) Bs[i] = W3[i];

    const int wid = tid >> 5, lane = tid & 31;
    // gather: warps 0-3 rows / c 0-31, warps 4-7 same rows / c 32-63
    {
        const int rbase = (wid & 3)*32 + lane;       // 0..127
        const int c0 = (wid >> 2)*32;
        const float* src = d_out2T + R0 + rbase;
#pragma unroll 4
        for (int cc = 0; cc < 32; cc++) {
            int c = c0 + cc;
            float v = __ldg(src + (size_t)c*ROWS_TOTAL);
            As[c*132 + rbase] = fmaxf(0.f, fmaf(v, __ldg(&g_scale2[c]), __ldg(&g_shift2[c])));
        }
    }
    __syncthreads();

    const int tc = tid & 15, tr = tid >> 4;
    float2 acc[4][8];   // [rowpair][col]
#pragma unroll
    for (int r = 0; r < 4; r++)
#pragma unroll
        for (int c = 0; c < 8; c++) acc[r][c] = make_float2(0.f, 0.f);

    for (int kk = 0; kk < 64; ++kk) {
        float4 a0 = *(const float4*)(As + kk*132 + tr*8);
        float4 a1 = *(const float4*)(As + kk*132 + tr*8 + 4);
        float2 ap[4] = { make_float2(a0.x,a0.y), make_float2(a0.z,a0.w),
                         make_float2(a1.x,a1.y), make_float2(a1.z,a1.w) };
        float4 q0 = *(const float4*)(Bs + kk*128 + tc*8);
        float4 q1 = *(const float4*)(Bs + kk*128 + tc*8 + 4);
        float2 bb[8] = { make_float2(q0.x,q0.x), make_float2(q0.y,q0.y),
                         make_float2(q0.z,q0.z), make_float2(q0.w,q0.w),
                         make_float2(q1.x,q1.x), make_float2(q1.y,q1.y),
                         make_float2(q1.z,q1.z), make_float2(q1.w,q1.w) };
#pragma unroll
        for (int r = 0; r < 4; r++)
#pragma unroll
            for (int c = 0; c < 8; c++)
                acc[r][c] = ffma2(ap[r], bb[c], acc[r][c]);
    }

    const int gl = tr >> 2;   // 8 rows of this thread lie in local group tr>>2
#pragma unroll
    for (int c = 0; c < 8; c++) {
        int col = tc*8 + c;
        float mx = -3.4e38f, mn = 3.4e38f, su = 0.f, sq = 0.f;
#pragma unroll
        for (int r = 0; r < 4; r++) {
            float v0 = acc[r][c].x, v1 = acc[r][c].y;
            mx = fmaxf(mx, fmaxf(v0, v1));
            mn = fminf(mn, fminf(v0, v1));
            su += v0 + v1; sq += v0*v0 + v1*v1;
        }
        atomicMax(&smax[gl*128 + col], enc_f(mx));
        atomicMin(&smin[gl*128 + col], enc_f(mn));
        atomicAdd(&ssum[col], su);
        atomicAdd(&ssq [col], sq);
    }
    __syncthreads();
    for (int i = tid; i < 512; i += 256) {
        d_gmax[(size_t)blockIdx.x*512 + i] = dec_f(smax[i]);
        d_gmin[(size_t)blockIdx.x*512 + i] = dec_f(smin[i]);
    }
    if (tid < 128) { atomicAdd(&g_sum3[tid], ssum[tid]); atomicAdd(&g_sq3[tid], ssq[tid]); }
}

// ---------------- prep: stats -> (scale, shift) ----------------
__global__ void prep_kernel(const float* __restrict__ g, const float* __restrict__ bt,
                            int layer) {
    int c = threadIdx.x;
    int C = (layer == 2) ? 128 : 64;
    if (c >= C) return;
    const float* sums = (layer==0) ? g_sum1 : (layer==1) ? g_sum2 : g_sum3;
    const float* sqs  = (layer==0) ? g_sq1  : (layer==1) ? g_sq2  : g_sq3;
    float* scp = (layer==0) ? g_scale1 : (layer==1) ? g_scale2 : g_scale3;
    float* shp = (layer==0) ? g_shift1 : (layer==1) ? g_shift2 : g_shift3;
    const float inv = 1.f / (float)ROWS_TOTAL;
    float m = sums[c] * inv;
    float v = fmaxf(sqs[c] * inv - m*m, 0.f);
    float s = g[c] * rsqrtf(v + 1e-5f);
    scp[c] = s;
    shp[c] = bt[c] - m * s;
}

// ---------------- finalize: pick max/min by BN sign, apply BN+relu ----------------
__global__ void finalize_kernel(float* __restrict__ outp) {
    int i = blockIdx.x * 256 + threadIdx.x;   // [group][channel] linear
    int c = i & 127;
    float s = g_scale3[c];
    float v = (s >= 0.f) ? d_gmax[i] : d_gmin[i];
    outp[i] = fmaxf(0.f, fmaf(s, v, g_shift3[c]));
}

// ---------------- launch ----------------
extern "C" void kernel_launch(void* const* d_in, const int* in_sizes, int n_in,
                              void* d_out, int out_size) {
    const float* xyz    = (const float*)d_in[0];
    const float* points = (const float*)d_in[1];
    const float* W1 = (const float*)d_in[2];
    const float* g1 = (const float*)d_in[3];
    const float* b1 = (const float*)d_in[4];
    const float* W2 = (const float*)d_in[5];
    const float* g2 = (const float*)d_in[6];
    const float* b2 = (const float*)d_in[7];
    const float* W3 = (const float*)d_in[8];
    const float* g3 = (const float*)d_in[9];
    const float* b3 = (const float*)d_in[10];

    float* out    = (float*)d_out;
    float* newxyz = out;                       // [8][2048][3]
    float* newpts = out + (size_t)B_*NPOINT*3; // [8][2048][128]

    cudaFuncSetAttribute(fps_kernel,   cudaFuncAttributeMaxDynamicSharedMemorySize, FPS_SMEM);
    cudaFuncSetAttribute(gemm1_kernel, cudaFuncAttributeMaxDynamicSharedMemorySize, G1_SMEM);
    cudaFuncSetAttribute(gemm2_kernel, cudaFuncAttributeMaxDynamicSharedMemorySize, G2_SMEM);
    cudaFuncSetAttribute(gemm3_kernel, cudaFuncAttributeMaxDynamicSharedMemorySize, G3_SMEM);
    cudaFuncSetAttribute(gemm1_kernel, cudaFuncAttributePreferredSharedMemoryCarveout, 100);
    cudaFuncSetAttribute(gemm2_kernel, cudaFuncAttributePreferredSharedMemoryCarveout, 100);
    cudaFuncSetAttribute(gemm3_kernel, cudaFuncAttributePreferredSharedMemoryCarveout, 100);
    cudaFuncSetAttribute(fps_kernel,   cudaFuncAttributePreferredSharedMemoryCarveout, 100);

    zero_stats<<<1, 128>>>();
    fps_kernel<<<B_, 1024, FPS_SMEM>>>(xyz, newxyz);
    ball_kernel<<<NGROUP/8, 256>>>(xyz, newxyz);
    gemm1_kernel<<<ROWS_TOTAL/128, 256, G1_SMEM>>>(xyz, points, W1, newxyz);
    prep_kernel<<<1, 128>>>(g1, b1, 0);
    gemm2_kernel<<<ROWS_TOTAL/128, 256, G2_SMEM>>>(W2);
    prep_kernel<<<1, 128>>>(g2, b2, 1);
    gemm3_kernel<<<ROWS_TOTAL/128, 256, G3_SMEM>>>(W3);
    prep_kernel<<<1, 128>>>(g3, b3, 2);
    finalize_kernel<<<(B_*NPOINT*128)/256, 256>>>(newpts);
}

// round 11
// speedup vs baseline: 1.1429x; 1.1429x over previous
#include <cuda_runtime.h>
#include <string.h>

// ---------------- problem constants ----------------
#define B_      8
#define N_      8192
#define C_      64
#define NPOINT  2048
#define NSAMPLE 32
#define ROWS_TOTAL (B_*NPOINT*NSAMPLE)   // 524288
#define NGROUP   (B_*NPOINT)             // 16384

// ---------------- device scratch (no cudaMalloc allowed) ----------------
__device__ int   d_ball[ROWS_TOTAL];
// transposed intermediates: [channel][row]
__device__ float d_out1T[(size_t)64*ROWS_TOTAL];
__device__ float d_out2T[(size_t)64*ROWS_TOTAL];
__device__ float d_gmax[(size_t)NGROUP*128];
__device__ float d_gmin[(size_t)NGROUP*128];

__device__ float g_sum1[64],  g_sq1[64];
__device__ float g_sum2[64],  g_sq2[64];
__device__ float g_sum3[128], g_sq3[128];
__device__ float g_scale1[64],  g_shift1[64];
__device__ float g_scale2[64],  g_shift2[64];
__device__ float g_scale3[128], g_shift3[128];

// ---------------- packed f32x2 helpers ----------------
__device__ __forceinline__ float2 ffma2(float2 a, float2 b, float2 c) {
    unsigned long long ua, ub, uc;
    memcpy(&ua, &a, 8); memcpy(&ub, &b, 8); memcpy(&uc, &c, 8);
    asm("fma.rn.f32x2 %0, %1, %2, %0;" : "+l"(uc) : "l"(ua), "l"(ub));
    float2 d; memcpy(&d, &uc, 8); return d;
}
__device__ __forceinline__ float2 fadd2(float2 a, float2 b) {
    unsigned long long ua, ub, uc;
    memcpy(&ua, &a, 8); memcpy(&ub, &b, 8);
    asm("add.rn.f32x2 %0, %1, %2;" : "=l"(uc) : "l"(ua), "l"(ub));
    float2 d; memcpy(&d, &uc, 8); return d;
}
__device__ __forceinline__ float2 fmul2(float2 a, float2 b) {
    unsigned long long ua, ub, uc;
    memcpy(&ua, &a, 8); memcpy(&ub, &b, 8);
    asm("mul.rn.f32x2 %0, %1, %2;" : "=l"(uc) : "l"(ua), "l"(ub));
    float2 d; memcpy(&d, &uc, 8); return d;
}

// warp-wide redux (sm_80+)
__device__ __forceinline__ unsigned redux_max_u32(unsigned v) {
    unsigned d; asm("redux.sync.max.u32 %0, %1, 0xffffffff;" : "=r"(d) : "r"(v)); return d;
}
__device__ __forceinline__ unsigned redux_min_u32(unsigned v) {
    unsigned d; asm("redux.sync.min.u32 %0, %1, 0xffffffff;" : "=r"(d) : "r"(v)); return d;
}

// order-preserving float<->uint for atomicMax/Min on signed floats
__device__ __forceinline__ unsigned enc_f(float f) {
    unsigned u = __float_as_uint(f);
    return (u & 0x80000000u) ? ~u : (u | 0x80000000u);
}
__device__ __forceinline__ float dec_f(unsigned u) {
    unsigned v = (u & 0x80000000u) ? (u & 0x7FFFFFFFu) : ~u;
    return __uint_as_float(v);
}
#define ENC_NEG_INF 0x007FFFFFu
#define ENC_POS_INF 0xFF800000u

// exact (non-FMA) squared distance, matching XLA f32: (dx*dx + dy*dy) + dz*dz
__device__ __forceinline__ float d2_exact(float dx, float dy, float dz) {
    return __fadd_rn(__fadd_rn(__fmul_rn(dx,dx), __fmul_rn(dy,dy)), __fmul_rn(dz,dz));
}

// ---------------- kernel 0: zero stats ----------------
__global__ void zero_stats() {
    int t = threadIdx.x;
    if (t < 64) { g_sum1[t]=0.f; g_sq1[t]=0.f; g_sum2[t]=0.f; g_sq2[t]=0.f; }
    if (t < 128){ g_sum3[t]=0.f; g_sq3[t]=0.f; }
}

// ---------------- kernel 1: furthest point sampling (r8, unchanged) ----------------
#define FPS_SMEM (3*N_*4 + NPOINT*4 + 2*64*4)
__global__ __launch_bounds__(1024, 1) void fps_kernel(const float* __restrict__ xyz,
                                                      float* __restrict__ newxyz) {
    extern __shared__ float sm[];
    float* xs = sm;
    float* ys = sm + N_;
    float* zs = sm + 2*N_;
    int*   picks = (int*)(sm + 3*N_);
    unsigned* sval = (unsigned*)(picks + NPOINT);  // [2][32]
    unsigned* sidx = sval + 64;                    // [2][32]

    const int b = blockIdx.x, tid = threadIdx.x;
    const int lane = tid & 31, wid = tid >> 5;
    const float* xb = xyz + (size_t)b * N_ * 3;

    for (int j = tid; j < 3*N_; j += 1024) {
        float v = xb[j];
        int p = j / 3, c = j - p*3;
        ((c == 0) ? xs : (c == 1) ? ys : zs)[p] = v;
    }
    if (tid == 0) picks[0] = 0;
    __syncthreads();

    float2 RX[4], RY[4], RZ[4];
    unsigned Du[8];
#pragma unroll
    for (int j = 0; j < 4; j++) {
        int p0 = tid + (2*j)*1024, p1 = p0 + 1024;
        RX[j] = make_float2(xs[p0], xs[p1]);
        RY[j] = make_float2(ys[p0], ys[p1]);
        RZ[j] = make_float2(zs[p0], zs[p1]);
        Du[2*j]   = __float_as_uint(1e10f);
        Du[2*j+1] = __float_as_uint(1e10f);
    }

    int last = 0;
    for (int it = 1; it < NPOINT; ++it) {
        float px = xs[last], py = ys[last], pz = zs[last];
        float2 nx2 = make_float2(-px, -px);
        float2 ny2 = make_float2(-py, -py);
        float2 nz2 = make_float2(-pz, -pz);

#pragma unroll
        for (int j = 0; j < 4; j++) {
            float2 dx = fadd2(RX[j], nx2);
            float2 dy = fadd2(RY[j], ny2);
            float2 dz = fadd2(RZ[j], nz2);
            float2 s  = fadd2(fadd2(fmul2(dx,dx), fmul2(dy,dy)), fmul2(dz,dz));
            Du[2*j]   = umin(Du[2*j],   __float_as_uint(s.x));
            Du[2*j+1] = umin(Du[2*j+1], __float_as_uint(s.y));
        }
        unsigned m01 = umax(Du[0], Du[1]), m23 = umax(Du[2], Du[3]);
        unsigned m45 = umax(Du[4], Du[5]), m67 = umax(Du[6], Du[7]);
        unsigned bv  = umax(umax(m01, m23), umax(m45, m67));

        unsigned wmax = redux_max_u32(bv);
        const int buf = (it & 1) << 5;
        if (lane == 0) sval[buf + wid] = wmax;
        __syncthreads();
        unsigned gm = redux_max_u32(sval[buf + lane]);   // global max value

        unsigned idxv = 0xFFFFFFFFu;
        if (wmax == gm) {                 // warp-uniform
            unsigned cand = 0xFFFFFFFFu;
            if (bv == gm) {
#pragma unroll
                for (int s = 7; s >= 0; --s)
                    if (Du[s] == gm) cand = (unsigned)(tid + (s << 10));
            }
            idxv = redux_min_u32(cand);
        }
        if (lane == 0) sidx[buf + wid] = idxv;
        __syncthreads();
        last = (int)redux_min_u32(sidx[buf + lane]);
        if (tid == 0) picks[it] = last;
    }
    __syncthreads();
    for (int s = tid; s < NPOINT; s += 1024) {
        int j = picks[s];
        float* o = newxyz + (size_t)(b*NPOINT + s)*3;
        o[0] = xs[j]; o[1] = ys[j]; o[2] = zs[j];
    }
}

// ---------------- kernel 2: ball query (warp-autonomous, unchanged) ----------------
__global__ __launch_bounds__(256) void ball_kernel(const float* __restrict__ xyz,
                                                   const float* __restrict__ nxyz) {
    __shared__ int sidx[8][32];
    const int lane = threadIdx.x & 31, w = threadIdx.x >> 5;
    const int g = blockIdx.x * 8 + w;           // global query id
    const int b = g >> 11;                      // 2048 queries per batch
    const float* qp = nxyz + (size_t)g * 3;
    const float qx = qp[0], qy = qp[1], qz = qp[2];
    const float R2f = (float)(0.4 * 0.4);
    const float* xb = xyz + (size_t)b * N_ * 3;

    int cnt = 0;
    for (int t0 = 0; t0 < N_; t0 += 32) {
        const int p = t0 + lane;
        const float* pp = xb + (size_t)p * 3;
        float x = __ldg(pp), y = __ldg(pp + 1), z = __ldg(pp + 2);
        float d2 = d2_exact(qx - x, qy - y, qz - z);
        bool ok = d2 < R2f;
        unsigned m = __ballot_sync(0xffffffffu, ok);
        if (m) {
            int pos = cnt + __popc(m & ((1u << lane) - 1u));
            if (ok && pos < 32) sidx[w][pos] = p;
            cnt += __popc(m);
            if (cnt >= 32) break;
        }
    }
    __syncwarp();
    int v = 0;
    if (cnt) {
        int first = sidx[w][0];
        v = (lane < cnt) ? sidx[w][lane] : first;
    }
    d_ball[((size_t)g << 5) + lane] = v;
}

// ================= GEMM micro-kernels =================
// r3-proven shape for gemm1/2: 256 threads, 128x64 tile, 8 rows x 4 cols per
// thread (tc = tid&15, tr = tid>>4). A k-major As[k*132+row], B [K][64].
// Per k: 2x LDS.128 A (broadcast) + 1x LDS.128 B feeding 16 FFMA2.
// 52.5/50 KB smem -> 4 blocks/SM -> 32 warps. Measured 150us in r3.
// Epilogues store transposed (d_outT) for the next gemm's coalesced gather.

// ---------------- GEMM 1: feats(gathered 67) @ W1 -> out1T + stats ----------------
#define G1_SMEM ((67*132 + 67*64)*4)
__global__ __launch_bounds__(256, 4) void gemm1_kernel(const float* __restrict__ xyz,
                                                       const float* __restrict__ points,
                                                       const float* __restrict__ W1,
                                                       const float* __restrict__ nxyz) {
    extern __shared__ float sm[];
    float* As = sm;             // [67][132] k-major
    float* Bs = sm + 67*132;    // [67][64]
    __shared__ float ssum[64], ssq[64];

    const int tid = threadIdx.x;
    const int R0 = blockIdx.x * 128;
    if (tid < 64) { ssum[tid] = 0.f; ssq[tid] = 0.f; }
    for (int i = tid; i < 67*64; i += 256) Bs[i] = W1[i];

    const int wid = tid >> 5, lane = tid & 31;
    for (int rr = wid; rr < 128; rr += 8) {
        int row = R0 + rr;
        int b = row >> 16, rem = row & 65535, s = rem >> 5;
        int j = d_ball[row];
        const float* prow = points + ((size_t)(b*N_ + j)) * 64;
        As[(3 + lane)*132 + rr]  = prow[lane];
        As[(35 + lane)*132 + rr] = prow[lane + 32];
        if (lane < 3)
            As[lane*132 + rr] = xyz[(size_t)(b*N_ + j)*3 + lane]
                              - nxyz[(size_t)(b*NPOINT + s)*3 + lane];
    }
    __syncthreads();

    const int tc = tid & 15, tr = tid >> 4;
    float2 acc[4][4];   // [rowpair][col]
#pragma unroll
    for (int r = 0; r < 4; r++)
#pragma unroll
        for (int c = 0; c < 4; c++) acc[r][c] = make_float2(0.f, 0.f);

    for (int kk = 0; kk < 67; ++kk) {
        float4 a0 = *(const float4*)(As + kk*132 + tr*8);
        float4 a1 = *(const float4*)(As + kk*132 + tr*8 + 4);
        float2 ap[4] = { make_float2(a0.x,a0.y), make_float2(a0.z,a0.w),
                         make_float2(a1.x,a1.y), make_float2(a1.z,a1.w) };
        float4 b4 = *(const float4*)(Bs + kk*64 + tc*4);
        float2 bb[4] = { make_float2(b4.x,b4.x), make_float2(b4.y,b4.y),
                         make_float2(b4.z,b4.z), make_float2(b4.w,b4.w) };
#pragma unroll
        for (int r = 0; r < 4; r++)
#pragma unroll
            for (int c = 0; c < 4; c++)
                acc[r][c] = ffma2(ap[r], bb[c], acc[r][c]);
    }

    // epilogue: transposed store (column-major) + stats
#pragma unroll
    for (int c = 0; c < 4; c++) {
        int col = tc*4 + c;
        float4 v0 = make_float4(acc[0][c].x, acc[0][c].y, acc[1][c].x, acc[1][c].y);
        float4 v1 = make_float4(acc[2][c].x, acc[2][c].y, acc[3][c].x, acc[3][c].y);
        *(float4*)(d_out1T + (size_t)col*ROWS_TOTAL + R0 + tr*8)     = v0;
        *(float4*)(d_out1T + (size_t)col*ROWS_TOTAL + R0 + tr*8 + 4) = v1;
        float su = v0.x+v0.y+v0.z+v0.w + v1.x+v1.y+v1.z+v1.w;
        float sq = v0.x*v0.x+v0.y*v0.y+v0.z*v0.z+v0.w*v0.w
                 + v1.x*v1.x+v1.y*v1.y+v1.z*v1.z+v1.w*v1.w;
        atomicAdd(&ssum[col], su);
        atomicAdd(&ssq [col], sq);
    }
    __syncthreads();
    if (tid < 64) { atomicAdd(&g_sum1[tid], ssum[tid]); atomicAdd(&g_sq1[tid], ssq[tid]); }
}

// ---------------- GEMM 2: relu(bn1(out1T)) @ W2 -> out2T + stats ----------------
#define G2_SMEM ((64*132 + 64*64)*4)
__global__ __launch_bounds__(256, 4) void gemm2_kernel(const float* __restrict__ W2) {
    extern __shared__ float sm[];
    float* As = sm;             // [64][132]
    float* Bs = sm + 64*132;    // [64][64]
    __shared__ float ssum[64], ssq[64];

    const int tid = threadIdx.x;
    const int R0 = blockIdx.x * 128;
    if (tid < 64) { ssum[tid] = 0.f; ssq[tid] = 0.f; }
    for (int i = tid; i < 64*64; i += 256) Bs[i] = W2[i];

    const int wid = tid >> 5, lane = tid & 31;
    // gather: warps 0-3 rows 0-127 / c 0-31, warps 4-7 same rows / c 32-63
    {
        const int rbase = (wid & 3)*32 + lane;       // 0..127
        const int c0 = (wid >> 2)*32;
        const float* src = d_out1T + R0 + rbase;
#pragma unroll 4
        for (int cc = 0; cc < 32; cc++) {
            int c = c0 + cc;
            float v = __ldg(src + (size_t)c*ROWS_TOTAL);
            As[c*132 + rbase] = fmaxf(0.f, fmaf(v, __ldg(&g_scale1[c]), __ldg(&g_shift1[c])));
        }
    }
    __syncthreads();

    const int tc = tid & 15, tr = tid >> 4;
    float2 acc[4][4];
#pragma unroll
    for (int r = 0; r < 4; r++)
#pragma unroll
        for (int c = 0; c < 4; c++) acc[r][c] = make_float2(0.f, 0.f);

    for (int kk = 0; kk < 64; ++kk) {
        float4 a0 = *(const float4*)(As + kk*132 + tr*8);
        float4 a1 = *(const float4*)(As + kk*132 + tr*8 + 4);
        float2 ap[4] = { make_float2(a0.x,a0.y), make_float2(a0.z,a0.w),
                         make_float2(a1.x,a1.y), make_float2(a1.z,a1.w) };
        float4 b4 = *(const float4*)(Bs + kk*64 + tc*4);
        float2 bb[4] = { make_float2(b4.x,b4.x), make_float2(b4.y,b4.y),
                         make_float2(b4.z,b4.z), make_float2(b4.w,b4.w) };
#pragma unroll
        for (int r = 0; r < 4; r++)
#pragma unroll
            for (int c = 0; c < 4; c++)
                acc[r][c] = ffma2(ap[r], bb[c], acc[r][c]);
    }

#pragma unroll
    for (int c = 0; c < 4; c++) {
        int col = tc*4 + c;
        float4 v0 = make_float4(acc[0][c].x, acc[0][c].y, acc[1][c].x, acc[1][c].y);
        float4 v1 = make_float4(acc[2][c].x, acc[2][c].y, acc[3][c].x, acc[3][c].y);
        *(float4*)(d_out2T + (size_t)col*ROWS_TOTAL + R0 + tr*8)     = v0;
        *(float4*)(d_out2T + (size_t)col*ROWS_TOTAL + R0 + tr*8 + 4) = v1;
        float su = v0.x+v0.y+v0.z+v0.w + v1.x+v1.y+v1.z+v1.w;
        float sq = v0.x*v0.x+v0.y*v0.y+v0.z*v0.z+v0.w*v0.w
                 + v1.x*v1.x+v1.y*v1.y+v1.z*v1.z+v1.w*v1.w;
        atomicAdd(&ssum[col], su);
        atomicAdd(&ssq [col], sq);
    }
    __syncthreads();
    if (tid < 64) { atomicAdd(&g_sum2[tid], ssum[tid]); atomicAdd(&g_sq2[tid], ssq[tid]); }
}

// ---------------- GEMM 3: relu(bn2(out2T)) @ W3 -> group max/min + stats ----------------
#define G3_SMEM ((64*132 + 64*128)*4)
__global__ __launch_bounds__(256) void gemm3_kernel(const float* __restrict__ W3) {
    extern __shared__ float sm[];
    float* As = sm;            // [64][132] k-major
    float* Bs = sm + 64*132;   // [64][128]
    __shared__ unsigned smax[512], smin[512];
    __shared__ float ssum[128], ssq[128];

    const int tid = threadIdx.x;
    const int R0 = blockIdx.x * 128;
    for (int i = tid; i < 512; i += 256) { smax[i] = ENC_NEG_INF; smin[i] = ENC_POS_INF; }
    if (tid < 128) { ssum[tid] = 0.f; ssq[tid] = 0.f; }
    for (int i = tid; i < 64*128; i += 256) Bs[i] = W3[i];

    const int wid = tid >> 5, lane = tid & 31;
    // gather: warps 0-3 rows / c 0-31, warps 4-7 same rows / c 32-63
    {
        const int rbase = (wid & 3)*32 + lane;       // 0..127
        const int c0 = (wid >> 2)*32;
        const float* src = d_out2T + R0 + rbase;
#pragma unroll 4
        for (int cc = 0; cc < 32; cc++) {
            int c = c0 + cc;
            float v = __ldg(src + (size_t)c*ROWS_TOTAL);
            As[c*132 + rbase] = fmaxf(0.f, fmaf(v, __ldg(&g_scale2[c]), __ldg(&g_shift2[c])));
        }
    }
    __syncthreads();

    const int tc = tid & 15, tr = tid >> 4;
    float2 acc[4][8];   // [rowpair][col]
#pragma unroll
    for (int r = 0; r < 4; r++)
#pragma unroll
        for (int c = 0; c < 8; c++) acc[r][c] = make_float2(0.f, 0.f);

    for (int kk = 0; kk < 64; ++kk) {
        float4 a0 = *(const float4*)(As + kk*132 + tr*8);
        float4 a1 = *(const float4*)(As + kk*132 + tr*8 + 4);
        float2 ap[4] = { make_float2(a0.x,a0.y), make_float2(a0.z,a0.w),
                         make_float2(a1.x,a1.y), make_float2(a1.z,a1.w) };
        float4 q0 = *(const float4*)(Bs + kk*128 + tc*8);
        float4 q1 = *(const float4*)(Bs + kk*128 + tc*8 + 4);
        float2 bb[8] = { make_float2(q0.x,q0.x), make_float2(q0.y,q0.y),
                         make_float2(q0.z,q0.z), make_float2(q0.w,q0.w),
                         make_float2(q1.x,q1.x), make_float2(q1.y,q1.y),
                         make_float2(q1.z,q1.z), make_float2(q1.w,q1.w) };
#pragma unroll
        for (int r = 0; r < 4; r++)
#pragma unroll
            for (int c = 0; c < 8; c++)
                acc[r][c] = ffma2(ap[r], bb[c], acc[r][c]);
    }

    const int gl = tr >> 2;   // 8 rows of this thread lie in local group tr>>2
#pragma unroll
    for (int c = 0; c < 8; c++) {
        int col = tc*8 + c;
        float mx = -3.4e38f, mn = 3.4e38f, su = 0.f, sq = 0.f;
#pragma unroll
        for (int r = 0; r < 4; r++) {
            float v0 = acc[r][c].x, v1 = acc[r][c].y;
            mx = fmaxf(mx, fmaxf(v0, v1));
            mn = fminf(mn, fminf(v0, v1));
            su += v0 + v1; sq += v0*v0 + v1*v1;
        }
        atomicMax(&smax[gl*128 + col], enc_f(mx));
        atomicMin(&smin[gl*128 + col], enc_f(mn));
        atomicAdd(&ssum[col], su);
        atomicAdd(&ssq [col], sq);
    }
    __syncthreads();
    for (int i = tid; i < 512; i += 256) {
        d_gmax[(size_t)blockIdx.x*512 + i] = dec_f(smax[i]);
        d_gmin[(size_t)blockIdx.x*512 + i] = dec_f(smin[i]);
    }
    if (tid < 128) { atomicAdd(&g_sum3[tid], ssum[tid]); atomicAdd(&g_sq3[tid], ssq[tid]); }
}

// ---------------- prep: stats -> (scale, shift) ----------------
__global__ void prep_kernel(const float* __restrict__ g, const float* __restrict__ bt,
                            int layer) {
    int c = threadIdx.x;
    int C = (layer == 2) ? 128 : 64;
    if (c >= C) return;
    const float* sums = (layer==0) ? g_sum1 : (layer==1) ? g_sum2 : g_sum3;
    const float* sqs  = (layer==0) ? g_sq1  : (layer==1) ? g_sq2  : g_sq3;
    float* scp = (layer==0) ? g_scale1 : (layer==1) ? g_scale2 : g_scale3;
    float* shp = (layer==0) ? g_shift1 : (layer==1) ? g_shift2 : g_shift3;
    const float inv = 1.f / (float)ROWS_TOTAL;
    float m = sums[c] * inv;
    float v = fmaxf(sqs[c] * inv - m*m, 0.f);
    float s = g[c] * rsqrtf(v + 1e-5f);
    scp[c] = s;
    shp[c] = bt[c] - m * s;
}

// ---------------- finalize: pick max/min by BN sign, apply BN+relu ----------------
__global__ void finalize_kernel(float* __restrict__ outp) {
    int i = blockIdx.x * 256 + threadIdx.x;   // [group][channel] linear
    int c = i & 127;
    float s = g_scale3[c];
    float v = (s >= 0.f) ? d_gmax[i] : d_gmin[i];
    outp[i] = fmaxf(0.f, fmaf(s, v, g_shift3[c]));
}

// ---------------- launch ----------------
extern "C" void kernel_launch(void* const* d_in, const int* in_sizes, int n_in,
                              void* d_out, int out_size) {
    const float* xyz    = (const float*)d_in[0];
    const float* points = (const float*)d_in[1];
    const float* W1 = (const float*)d_in[2];
    const float* g1 = (const float*)d_in[3];
    const float* b1 = (const float*)d_in[4];
    const float* W2 = (const float*)d_in[5];
    const float* g2 = (const float*)d_in[6];
    const float* b2 = (const float*)d_in[7];
    const float* W3 = (const float*)d_in[8];
    const float* g3 = (const float*)d_in[9];
    const float* b3 = (const float*)d_in[10];

    float* out    = (float*)d_out;
    float* newxyz = out;                       // [8][2048][3]
    float* newpts = out + (size_t)B_*NPOINT*3; // [8][2048][128]

    cudaFuncSetAttribute(fps_kernel,   cudaFuncAttributeMaxDynamicSharedMemorySize, FPS_SMEM);
    cudaFuncSetAttribute(gemm1_kernel, cudaFuncAttributeMaxDynamicSharedMemorySize, G1_SMEM);
    cudaFuncSetAttribute(gemm2_kernel, cudaFuncAttributeMaxDynamicSharedMemorySize, G2_SMEM);
    cudaFuncSetAttribute(gemm3_kernel, cudaFuncAttributeMaxDynamicSharedMemorySize, G3_SMEM);
    cudaFuncSetAttribute(fps_kernel,   cudaFuncAttributePreferredSharedMemoryCarveout, 100);

    zero_stats<<<1, 128>>>();
    fps_kernel<<<B_, 1024, FPS_SMEM>>>(xyz, newxyz);
    ball_kernel<<<NGROUP/8, 256>>>(xyz, newxyz);
    gemm1_kernel<<<ROWS_TOTAL/128, 256, G1_SMEM>>>(xyz, points, W1, newxyz);
    prep_kernel<<<1, 128>>>(g1, b1, 0);
    gemm2_kernel<<<ROWS_TOTAL/128, 256, G2_SMEM>>>(W2);
    prep_kernel<<<1, 128>>>(g2, b2, 1);
    gemm3_kernel<<<ROWS_TOTAL/128, 256, G3_SMEM>>>(W3);
    prep_kernel<<<1, 128>>>(g3, b3, 2);
    finalize_kernel<<<(B_*NPOINT*128)/256, 256>>>(newpts);
}

// round 12
// speedup vs baseline: 1.1791x; 1.0316x over previous
#include <cuda_runtime.h>
#include <string.h>

// ---------------- problem constants ----------------
#define B_      8
#define N_      8192
#define C_      64
#define NPOINT  2048
#define NSAMPLE 32
#define ROWS_TOTAL (B_*NPOINT*NSAMPLE)   // 524288
#define NGROUP   (B_*NPOINT)             // 16384

// ---------------- device scratch (no cudaMalloc allowed) ----------------
__device__ int   d_ball[ROWS_TOTAL];
// transposed intermediates: [channel][row]
__device__ float d_out1T[(size_t)64*ROWS_TOTAL];
__device__ float d_out2T[(size_t)64*ROWS_TOTAL];
__device__ float d_gmax[(size_t)NGROUP*128];
__device__ float d_gmin[(size_t)NGROUP*128];

__device__ float g_sum1[64],  g_sq1[64];
__device__ float g_sum2[64],  g_sq2[64];
__device__ float g_sum3[128], g_sq3[128];
__device__ float g_scale1[64],  g_shift1[64];
__device__ float g_scale2[64],  g_shift2[64];
__device__ float g_scale3[128], g_shift3[128];

// ---------------- packed f32x2 helpers ----------------
__device__ __forceinline__ float2 ffma2(float2 a, float2 b, float2 c) {
    unsigned long long ua, ub, uc;
    memcpy(&ua, &a, 8); memcpy(&ub, &b, 8); memcpy(&uc, &c, 8);
    asm("fma.rn.f32x2 %0, %1, %2, %0;" : "+l"(uc) : "l"(ua), "l"(ub));
    float2 d; memcpy(&d, &uc, 8); return d;
}
__device__ __forceinline__ float2 fadd2(float2 a, float2 b) {
    unsigned long long ua, ub, uc;
    memcpy(&ua, &a, 8); memcpy(&ub, &b, 8);
    asm("add.rn.f32x2 %0, %1, %2;" : "=l"(uc) : "l"(ua), "l"(ub));
    float2 d; memcpy(&d, &uc, 8); return d;
}
__device__ __forceinline__ float2 fmul2(float2 a, float2 b) {
    unsigned long long ua, ub, uc;
    memcpy(&ua, &a, 8); memcpy(&ub, &b, 8);
    asm("mul.rn.f32x2 %0, %1, %2;" : "=l"(uc) : "l"(ua), "l"(ub));
    float2 d; memcpy(&d, &uc, 8); return d;
}

// warp-wide redux (sm_80+)
__device__ __forceinline__ unsigned redux_max_u32(unsigned v) {
    unsigned d; asm("redux.sync.max.u32 %0, %1, 0xffffffff;" : "=r"(d) : "r"(v)); return d;
}
__device__ __forceinline__ unsigned redux_min_u32(unsigned v) {
    unsigned d; asm("redux.sync.min.u32 %0, %1, 0xffffffff;" : "=r"(d) : "r"(v)); return d;
}

// order-preserving float<->uint for atomicMax/Min on signed floats
__device__ __forceinline__ unsigned enc_f(float f) {
    unsigned u = __float_as_uint(f);
    return (u & 0x80000000u) ? ~u : (u | 0x80000000u);
}
__device__ __forceinline__ float dec_f(unsigned u) {
    unsigned v = (u & 0x80000000u) ? (u & 0x7FFFFFFFu) : ~u;
    return __uint_as_float(v);
}
#define ENC_NEG_INF 0x007FFFFFu
#define ENC_POS_INF 0xFF800000u

// exact (non-FMA) squared distance, matching XLA f32: (dx*dx + dy*dy) + dz*dz
__device__ __forceinline__ float d2_exact(float dx, float dy, float dz) {
    return __fadd_rn(__fadd_rn(__fmul_rn(dx,dx), __fmul_rn(dy,dy)), __fmul_rn(dz,dz));
}

// ---------------- kernel 0: zero stats ----------------
__global__ void zero_stats() {
    int t = threadIdx.x;
    if (t < 64) { g_sum1[t]=0.f; g_sq1[t]=0.f; g_sum2[t]=0.f; g_sq2[t]=0.f; }
    if (t < 128){ g_sum3[t]=0.f; g_sq3[t]=0.f; }
}

// ---------------- kernel 1: furthest point sampling (r8, unchanged) ----------------
#define FPS_SMEM (3*N_*4 + NPOINT*4 + 2*64*4)
__global__ __launch_bounds__(1024, 1) void fps_kernel(const float* __restrict__ xyz,
                                                      float* __restrict__ newxyz) {
    extern __shared__ float sm[];
    float* xs = sm;
    float* ys = sm + N_;
    float* zs = sm + 2*N_;
    int*   picks = (int*)(sm + 3*N_);
    unsigned* sval = (unsigned*)(picks + NPOINT);  // [2][32]
    unsigned* sidx = sval + 64;                    // [2][32]

    const int b = blockIdx.x, tid = threadIdx.x;
    const int lane = tid & 31, wid = tid >> 5;
    const float* xb = xyz + (size_t)b * N_ * 3;

    for (int j = tid; j < 3*N_; j += 1024) {
        float v = xb[j];
        int p = j / 3, c = j - p*3;
        ((c == 0) ? xs : (c == 1) ? ys : zs)[p] = v;
    }
    if (tid == 0) picks[0] = 0;
    __syncthreads();

    float2 RX[4], RY[4], RZ[4];
    unsigned Du[8];
#pragma unroll
    for (int j = 0; j < 4; j++) {
        int p0 = tid + (2*j)*1024, p1 = p0 + 1024;
        RX[j] = make_float2(xs[p0], xs[p1]);
        RY[j] = make_float2(ys[p0], ys[p1]);
        RZ[j] = make_float2(zs[p0], zs[p1]);
        Du[2*j]   = __float_as_uint(1e10f);
        Du[2*j+1] = __float_as_uint(1e10f);
    }

    int last = 0;
    for (int it = 1; it < NPOINT; ++it) {
        float px = xs[last], py = ys[last], pz = zs[last];
        float2 nx2 = make_float2(-px, -px);
        float2 ny2 = make_float2(-py, -py);
        float2 nz2 = make_float2(-pz, -pz);

#pragma unroll
        for (int j = 0; j < 4; j++) {
            float2 dx = fadd2(RX[j], nx2);
            float2 dy = fadd2(RY[j], ny2);
            float2 dz = fadd2(RZ[j], nz2);
            float2 s  = fadd2(fadd2(fmul2(dx,dx), fmul2(dy,dy)), fmul2(dz,dz));
            Du[2*j]   = umin(Du[2*j],   __float_as_uint(s.x));
            Du[2*j+1] = umin(Du[2*j+1], __float_as_uint(s.y));
        }
        unsigned m01 = umax(Du[0], Du[1]), m23 = umax(Du[2], Du[3]);
        unsigned m45 = umax(Du[4], Du[5]), m67 = umax(Du[6], Du[7]);
        unsigned bv  = umax(umax(m01, m23), umax(m45, m67));

        unsigned wmax = redux_max_u32(bv);
        const int buf = (it & 1) << 5;
        if (lane == 0) sval[buf + wid] = wmax;
        __syncthreads();
        unsigned gm = redux_max_u32(sval[buf + lane]);   // global max value

        unsigned idxv = 0xFFFFFFFFu;
        if (wmax == gm) {                 // warp-uniform
            unsigned cand = 0xFFFFFFFFu;
            if (bv == gm) {
#pragma unroll
                for (int s = 7; s >= 0; --s)
                    if (Du[s] == gm) cand = (unsigned)(tid + (s << 10));
            }
            idxv = redux_min_u32(cand);
        }
        if (lane == 0) sidx[buf + wid] = idxv;
        __syncthreads();
        last = (int)redux_min_u32(sidx[buf + lane]);
        if (tid == 0) picks[it] = last;
    }
    __syncthreads();
    for (int s = tid; s < NPOINT; s += 1024) {
        int j = picks[s];
        float* o = newxyz + (size_t)(b*NPOINT + s)*3;
        o[0] = xs[j]; o[1] = ys[j]; o[2] = zs[j];
    }
}

// ---------------- kernel 2: ball query (warp-autonomous, unchanged) ----------------
__global__ __launch_bounds__(256) void ball_kernel(const float* __restrict__ xyz,
                                                   const float* __restrict__ nxyz) {
    __shared__ int sidx[8][32];
    const int lane = threadIdx.x & 31, w = threadIdx.x >> 5;
    const int g = blockIdx.x * 8 + w;           // global query id
    const int b = g >> 11;                      // 2048 queries per batch
    const float* qp = nxyz + (size_t)g * 3;
    const float qx = qp[0], qy = qp[1], qz = qp[2];
    const float R2f = (float)(0.4 * 0.4);
    const float* xb = xyz + (size_t)b * N_ * 3;

    int cnt = 0;
    for (int t0 = 0; t0 < N_; t0 += 32) {
        const int p = t0 + lane;
        const float* pp = xb + (size_t)p * 3;
        float x = __ldg(pp), y = __ldg(pp + 1), z = __ldg(pp + 2);
        float d2 = d2_exact(qx - x, qy - y, qz - z);
        bool ok = d2 < R2f;
        unsigned m = __ballot_sync(0xffffffffu, ok);
        if (m) {
            int pos = cnt + __popc(m & ((1u << lane) - 1u));
            if (ok && pos < 32) sidx[w][pos] = p;
            cnt += __popc(m);
            if (cnt >= 32) break;
        }
    }
    __syncwarp();
    int v = 0;
    if (cnt) {
        int first = sidx[w][0];
        v = (lane < cnt) ? sidx[w][lane] : first;
    }
    d_ball[((size_t)g << 5) + lane] = v;
}

// ================= GEMM micro-kernels (r11 mainloops) =================
// Epilogue change (r12): tid^16 flips bit0 of tr -> same warp, same cols, same
// group. One shfl_xor(16) butterfly merges two threads' partials; only even-tr
// threads issue shared atomics -> half the ATOMS LSU traffic.

// ---------------- GEMM 1: feats(gathered 67) @ W1 -> out1T + stats ----------------
#define G1_SMEM ((67*132 + 67*64)*4)
__global__ __launch_bounds__(256, 4) void gemm1_kernel(const float* __restrict__ xyz,
                                                       const float* __restrict__ points,
                                                       const float* __restrict__ W1,
                                                       const float* __restrict__ nxyz) {
    extern __shared__ float sm[];
    float* As = sm;             // [67][132] k-major
    float* Bs = sm + 67*132;    // [67][64]
    __shared__ float ssum[64], ssq[64];

    const int tid = threadIdx.x;
    const int R0 = blockIdx.x * 128;
    if (tid < 64) { ssum[tid] = 0.f; ssq[tid] = 0.f; }
    for (int i = tid; i < 67*64; i += 256) Bs[i] = W1[i];

    const int wid = tid >> 5, lane = tid & 31;
    for (int rr = wid; rr < 128; rr += 8) {
        int row = R0 + rr;
        int b = row >> 16, rem = row & 65535, s = rem >> 5;
        int j = d_ball[row];
        const float* prow = points + ((size_t)(b*N_ + j)) * 64;
        As[(3 + lane)*132 + rr]  = prow[lane];
        As[(35 + lane)*132 + rr] = prow[lane + 32];
        if (lane < 3)
            As[lane*132 + rr] = xyz[(size_t)(b*N_ + j)*3 + lane]
                              - nxyz[(size_t)(b*NPOINT + s)*3 + lane];
    }
    __syncthreads();

    const int tc = tid & 15, tr = tid >> 4;
    float2 acc[4][4];   // [rowpair][col]
#pragma unroll
    for (int r = 0; r < 4; r++)
#pragma unroll
        for (int c = 0; c < 4; c++) acc[r][c] = make_float2(0.f, 0.f);

    for (int kk = 0; kk < 67; ++kk) {
        float4 a0 = *(const float4*)(As + kk*132 + tr*8);
        float4 a1 = *(const float4*)(As + kk*132 + tr*8 + 4);
        float2 ap[4] = { make_float2(a0.x,a0.y), make_float2(a0.z,a0.w),
                         make_float2(a1.x,a1.y), make_float2(a1.z,a1.w) };
        float4 b4 = *(const float4*)(Bs + kk*64 + tc*4);
        float2 bb[4] = { make_float2(b4.x,b4.x), make_float2(b4.y,b4.y),
                         make_float2(b4.z,b4.z), make_float2(b4.w,b4.w) };
#pragma unroll
        for (int r = 0; r < 4; r++)
#pragma unroll
            for (int c = 0; c < 4; c++)
                acc[r][c] = ffma2(ap[r], bb[c], acc[r][c]);
    }

    // epilogue: transposed store (column-major) + stats (shfl pre-combine)
    float cs[4], cq[4];
#pragma unroll
    for (int c = 0; c < 4; c++) {
        int col = tc*4 + c;
        float4 v0 = make_float4(acc[0][c].x, acc[0][c].y, acc[1][c].x, acc[1][c].y);
        float4 v1 = make_float4(acc[2][c].x, acc[2][c].y, acc[3][c].x, acc[3][c].y);
        *(float4*)(d_out1T + (size_t)col*ROWS_TOTAL + R0 + tr*8)     = v0;
        *(float4*)(d_out1T + (size_t)col*ROWS_TOTAL + R0 + tr*8 + 4) = v1;
        cs[c] = v0.x+v0.y+v0.z+v0.w + v1.x+v1.y+v1.z+v1.w;
        cq[c] = v0.x*v0.x+v0.y*v0.y+v0.z*v0.z+v0.w*v0.w
              + v1.x*v1.x+v1.y*v1.y+v1.z*v1.z+v1.w*v1.w;
    }
#pragma unroll
    for (int c = 0; c < 4; c++) {
        cs[c] += __shfl_xor_sync(0xffffffffu, cs[c], 16);
        cq[c] += __shfl_xor_sync(0xffffffffu, cq[c], 16);
    }
    if (!(tr & 1)) {
#pragma unroll
        for (int c = 0; c < 4; c++) {
            atomicAdd(&ssum[tc*4+c], cs[c]);
            atomicAdd(&ssq [tc*4+c], cq[c]);
        }
    }
    __syncthreads();
    if (tid < 64) { atomicAdd(&g_sum1[tid], ssum[tid]); atomicAdd(&g_sq1[tid], ssq[tid]); }
}

// ---------------- GEMM 2: relu(bn1(out1T)) @ W2 -> out2T + stats ----------------
#define G2_SMEM ((64*132 + 64*64)*4)
__global__ __launch_bounds__(256, 4) void gemm2_kernel(const float* __restrict__ W2) {
    extern __shared__ float sm[];
    float* As = sm;             // [64][132]
    float* Bs = sm + 64*132;    // [64][64]
    __shared__ float ssum[64], ssq[64];

    const int tid = threadIdx.x;
    const int R0 = blockIdx.x * 128;
    if (tid < 64) { ssum[tid] = 0.f; ssq[tid] = 0.f; }
    for (int i = tid; i < 64*64; i += 256) Bs[i] = W2[i];

    const int wid = tid >> 5, lane = tid & 31;
    // gather: warps 0-3 rows 0-127 / c 0-31, warps 4-7 same rows / c 32-63
    {
        const int rbase = (wid & 3)*32 + lane;       // 0..127
        const int c0 = (wid >> 2)*32;
        const float* src = d_out1T + R0 + rbase;
#pragma unroll 4
        for (int cc = 0; cc < 32; cc++) {
            int c = c0 + cc;
            float v = __ldg(src + (size_t)c*ROWS_TOTAL);
            As[c*132 + rbase] = fmaxf(0.f, fmaf(v, __ldg(&g_scale1[c]), __ldg(&g_shift1[c])));
        }
    }
    __syncthreads();

    const int tc = tid & 15, tr = tid >> 4;
    float2 acc[4][4];
#pragma unroll
    for (int r = 0; r < 4; r++)
#pragma unroll
        for (int c = 0; c < 4; c++) acc[r][c] = make_float2(0.f, 0.f);

    for (int kk = 0; kk < 64; ++kk) {
        float4 a0 = *(const float4*)(As + kk*132 + tr*8);
        float4 a1 = *(const float4*)(As + kk*132 + tr*8 + 4);
        float2 ap[4] = { make_float2(a0.x,a0.y), make_float2(a0.z,a0.w),
                         make_float2(a1.x,a1.y), make_float2(a1.z,a1.w) };
        float4 b4 = *(const float4*)(Bs + kk*64 + tc*4);
        float2 bb[4] = { make_float2(b4.x,b4.x), make_float2(b4.y,b4.y),
                         make_float2(b4.z,b4.z), make_float2(b4.w,b4.w) };
#pragma unroll
        for (int r = 0; r < 4; r++)
#pragma unroll
            for (int c = 0; c < 4; c++)
                acc[r][c] = ffma2(ap[r], bb[c], acc[r][c]);
    }

    float cs[4], cq[4];
#pragma unroll
    for (int c = 0; c < 4; c++) {
        int col = tc*4 + c;
        float4 v0 = make_float4(acc[0][c].x, acc[0][c].y, acc[1][c].x, acc[1][c].y);
        float4 v1 = make_float4(acc[2][c].x, acc[2][c].y, acc[3][c].x, acc[3][c].y);
        *(float4*)(d_out2T + (size_t)col*ROWS_TOTAL + R0 + tr*8)     = v0;
        *(float4*)(d_out2T + (size_t)col*ROWS_TOTAL + R0 + tr*8 + 4) = v1;
        cs[c] = v0.x+v0.y+v0.z+v0.w + v1.x+v1.y+v1.z+v1.w;
        cq[c] = v0.x*v0.x+v0.y*v0.y+v0.z*v0.z+v0.w*v0.w
              + v1.x*v1.x+v1.y*v1.y+v1.z*v1.z+v1.w*v1.w;
    }
#pragma unroll
    for (int c = 0; c < 4; c++) {
        cs[c] += __shfl_xor_sync(0xffffffffu, cs[c], 16);
        cq[c] += __shfl_xor_sync(0xffffffffu, cq[c], 16);
    }
    if (!(tr & 1)) {
#pragma unroll
        for (int c = 0; c < 4; c++) {
            atomicAdd(&ssum[tc*4+c], cs[c]);
            atomicAdd(&ssq [tc*4+c], cq[c]);
        }
    }
    __syncthreads();
    if (tid < 64) { atomicAdd(&g_sum2[tid], ssum[tid]); atomicAdd(&g_sq2[tid], ssq[tid]); }
}

// ---------------- GEMM 3: relu(bn2(out2T)) @ W3 -> group max/min + stats ----------------
#define G3_SMEM ((64*132 + 64*128)*4)
__global__ __launch_bounds__(256) void gemm3_kernel(const float* __restrict__ W3) {
    extern __shared__ float sm[];
    float* As = sm;            // [64][132] k-major
    float* Bs = sm + 64*132;   // [64][128]
    __shared__ unsigned smax[512], smin[512];
    __shared__ float ssum[128], ssq[128];

    const int tid = threadIdx.x;
    const int R0 = blockIdx.x * 128;
    for (int i = tid; i < 512; i += 256) { smax[i] = ENC_NEG_INF; smin[i] = ENC_POS_INF; }
    if (tid < 128) { ssum[tid] = 0.f; ssq[tid] = 0.f; }
    for (int i = tid; i < 64*128; i += 256) Bs[i] = W3[i];

    const int wid = tid >> 5, lane = tid & 31;
    // gather: warps 0-3 rows / c 0-31, warps 4-7 same rows / c 32-63
    {
        const int rbase = (wid & 3)*32 + lane;       // 0..127
        const int c0 = (wid >> 2)*32;
        const float* src = d_out2T + R0 + rbase;
#pragma unroll 4
        for (int cc = 0; cc < 32; cc++) {
            int c = c0 + cc;
            float v = __ldg(src + (size_t)c*ROWS_TOTAL);
            As[c*132 + rbase] = fmaxf(0.f, fmaf(v, __ldg(&g_scale2[c]), __ldg(&g_shift2[c])));
        }
    }
    __syncthreads();

    const int tc = tid & 15, tr = tid >> 4;
    float2 acc[4][8];   // [rowpair][col]
#pragma unroll
    for (int r = 0; r < 4; r++)
#pragma unroll
        for (int c = 0; c < 8; c++) acc[r][c] = make_float2(0.f, 0.f);

    for (int kk = 0; kk < 64; ++kk) {
        float4 a0 = *(const float4*)(As + kk*132 + tr*8);
        float4 a1 = *(const float4*)(As + kk*132 + tr*8 + 4);
        float2 ap[4] = { make_float2(a0.x,a0.y), make_float2(a0.z,a0.w),
                         make_float2(a1.x,a1.y), make_float2(a1.z,a1.w) };
        float4 q0 = *(const float4*)(Bs + kk*128 + tc*8);
        float4 q1 = *(const float4*)(Bs + kk*128 + tc*8 + 4);
        float2 bb[8] = { make_float2(q0.x,q0.x), make_float2(q0.y,q0.y),
                         make_float2(q0.z,q0.z), make_float2(q0.w,q0.w),
                         make_float2(q1.x,q1.x), make_float2(q1.y,q1.y),
                         make_float2(q1.z,q1.z), make_float2(q1.w,q1.w) };
#pragma unroll
        for (int r = 0; r < 4; r++)
#pragma unroll
            for (int c = 0; c < 8; c++)
                acc[r][c] = ffma2(ap[r], bb[c], acc[r][c]);
    }

    const int gl = tr >> 2;   // 8 rows of this thread lie in local group tr>>2
#pragma unroll
    for (int c = 0; c < 8; c++) {
        int col = tc*8 + c;
        float mx = -3.4e38f, mn = 3.4e38f, su = 0.f, sq = 0.f;
#pragma unroll
        for (int r = 0; r < 4; r++) {
            float v0 = acc[r][c].x, v1 = acc[r][c].y;
            mx = fmaxf(mx, fmaxf(v0, v1));
            mn = fminf(mn, fminf(v0, v1));
            su += v0 + v1; sq += v0*v0 + v1*v1;
        }
        // shfl pre-combine: tid^16 = tr^1 -> same warp, same col, same gl
        mx = fmaxf(mx, __shfl_xor_sync(0xffffffffu, mx, 16));
        mn = fminf(mn, __shfl_xor_sync(0xffffffffu, mn, 16));
        su += __shfl_xor_sync(0xffffffffu, su, 16);
        sq += __shfl_xor_sync(0xffffffffu, sq, 16);
        if (!(tr & 1)) {
            atomicMax(&smax[gl*128 + col], enc_f(mx));
            atomicMin(&smin[gl*128 + col], enc_f(mn));
            atomicAdd(&ssum[col], su);
            atomicAdd(&ssq [col], sq);
        }
    }
    __syncthreads();
    for (int i = tid; i < 512; i += 256) {
        d_gmax[(size_t)blockIdx.x*512 + i] = dec_f(smax[i]);
        d_gmin[(size_t)blockIdx.x*512 + i] = dec_f(smin[i]);
    }
    if (tid < 128) { atomicAdd(&g_sum3[tid], ssum[tid]); atomicAdd(&g_sq3[tid], ssq[tid]); }
}

// ---------------- prep: stats -> (scale, shift) ----------------
__global__ void prep_kernel(const float* __restrict__ g, const float* __restrict__ bt,
                            int layer) {
    int c = threadIdx.x;
    int C = (layer == 2) ? 128 : 64;
    if (c >= C) return;
    const float* sums = (layer==0) ? g_sum1 : (layer==1) ? g_sum2 : g_sum3;
    const float* sqs  = (layer==0) ? g_sq1  : (layer==1) ? g_sq2  : g_sq3;
    float* scp = (layer==0) ? g_scale1 : (layer==1) ? g_scale2 : g_scale3;
    float* shp = (layer==0) ? g_shift1 : (layer==1) ? g_shift2 : g_shift3;
    const float inv = 1.f / (float)ROWS_TOTAL;
    float m = sums[c] * inv;
    float v = fmaxf(sqs[c] * inv - m*m, 0.f);
    float s = g[c] * rsqrtf(v + 1e-5f);
    scp[c] = s;
    shp[c] = bt[c] - m * s;
}

// ---------------- finalize: pick max/min by BN sign, apply BN+relu ----------------
__global__ void finalize_kernel(float* __restrict__ outp) {
    int i = blockIdx.x * 256 + threadIdx.x;   // [group][channel] linear
    int c = i & 127;
    float s = g_scale3[c];
    float v = (s >= 0.f) ? d_gmax[i] : d_gmin[i];
    outp[i] = fmaxf(0.f, fmaf(s, v, g_shift3[c]));
}

// ---------------- launch ----------------
extern "C" void kernel_launch(void* const* d_in, const int* in_sizes, int n_in,
                              void* d_out, int out_size) {
    const float* xyz    = (const float*)d_in[0];
    const float* points = (const float*)d_in[1];
    const float* W1 = (const float*)d_in[2];
    const float* g1 = (const float*)d_in[3];
    const float* b1 = (const float*)d_in[4];
    const float* W2 = (const float*)d_in[5];
    const float* g2 = (const float*)d_in[6];
    const float* b2 = (const float*)d_in[7];
    const float* W3 = (const float*)d_in[8];
    const float* g3 = (const float*)d_in[9];
    const float* b3 = (const float*)d_in[10];

    float* out    = (float*)d_out;
    float* newxyz = out;                       // [8][2048][3]
    float* newpts = out + (size_t)B_*NPOINT*3; // [8][2048][128]

    cudaFuncSetAttribute(fps_kernel,   cudaFuncAttributeMaxDynamicSharedMemorySize, FPS_SMEM);
    cudaFuncSetAttribute(gemm1_kernel, cudaFuncAttributeMaxDynamicSharedMemorySize, G1_SMEM);
    cudaFuncSetAttribute(gemm2_kernel, cudaFuncAttributeMaxDynamicSharedMemorySize, G2_SMEM);
    cudaFuncSetAttribute(gemm3_kernel, cudaFuncAttributeMaxDynamicSharedMemorySize, G3_SMEM);
    cudaFuncSetAttribute(fps_kernel,   cudaFuncAttributePreferredSharedMemoryCarveout, 100);

    zero_stats<<<1, 128>>>();
    fps_kernel<<<B_, 1024, FPS_SMEM>>>(xyz, newxyz);
    ball_kernel<<<NGROUP/8, 256>>>(xyz, newxyz);
    gemm1_kernel<<<ROWS_TOTAL/128, 256, G1_SMEM>>>(xyz, points, W1, newxyz);
    prep_kernel<<<1, 128>>>(g1, b1, 0);
    gemm2_kernel<<<ROWS_TOTAL/128, 256, G2_SMEM>>>(W2);
    prep_kernel<<<1, 128>>>(g2, b2, 1);
    gemm3_kernel<<<ROWS_TOTAL/128, 256, G3_SMEM>>>(W3);
    prep_kernel<<<1, 128>>>(g3, b3, 2);
    finalize_kernel<<<(B_*NPOINT*128)/256, 256>>>(newpts);
}

// round 14
// speedup vs baseline: 1.2371x; 1.0492x over previous
#include <cuda_runtime.h>
#include <string.h>

// ---------------- problem constants ----------------
#define B_      8
#define N_      8192
#define C_      64
#define NPOINT  2048
#define NSAMPLE 32
#define ROWS_TOTAL (B_*NPOINT*NSAMPLE)   // 524288
#define NGROUP   (B_*NPOINT)             // 16384

// ---------------- device scratch (no cudaMalloc allowed) ----------------
__device__ int   d_ball[ROWS_TOTAL];
// transposed intermediates: [channel][row]
__device__ float d_out1T[(size_t)64*ROWS_TOTAL];
__device__ float d_out2T[(size_t)64*ROWS_TOTAL];
__device__ float d_gmax[(size_t)NGROUP*128];
__device__ float d_gmin[(size_t)NGROUP*128];

__device__ float g_sum1[64],  g_sq1[64];
__device__ float g_sum2[64],  g_sq2[64];
__device__ float g_sum3[128], g_sq3[128];
__device__ float g_scale1[64],  g_shift1[64];
__device__ float g_scale2[64],  g_shift2[64];
__device__ float g_scale3[128], g_shift3[128];

// ---------------- packed f32x2 helpers ----------------
__device__ __forceinline__ float2 ffma2(float2 a, float2 b, float2 c) {
    unsigned long long ua, ub, uc;
    memcpy(&ua, &a, 8); memcpy(&ub, &b, 8); memcpy(&uc, &c, 8);
    asm("fma.rn.f32x2 %0, %1, %2, %0;" : "+l"(uc) : "l"(ua), "l"(ub));
    float2 d; memcpy(&d, &uc, 8); return d;
}
__device__ __forceinline__ float2 fadd2(float2 a, float2 b) {
    unsigned long long ua, ub, uc;
    memcpy(&ua, &a, 8); memcpy(&ub, &b, 8);
    asm("add.rn.f32x2 %0, %1, %2;" : "=l"(uc) : "l"(ua), "l"(ub));
    float2 d; memcpy(&d, &uc, 8); return d;
}
__device__ __forceinline__ float2 fmul2(float2 a, float2 b) {
    unsigned long long ua, ub, uc;
    memcpy(&ua, &a, 8); memcpy(&ub, &b, 8);
    asm("mul.rn.f32x2 %0, %1, %2;" : "=l"(uc) : "l"(ua), "l"(ub));
    float2 d; memcpy(&d, &uc, 8); return d;
}

// warp-wide redux (sm_80+)
__device__ __forceinline__ unsigned redux_max_u32(unsigned v) {
    unsigned d; asm("redux.sync.max.u32 %0, %1, 0xffffffff;" : "=r"(d) : "r"(v)); return d;
}
__device__ __forceinline__ unsigned redux_min_u32(unsigned v) {
    unsigned d; asm("redux.sync.min.u32 %0, %1, 0xffffffff;" : "=r"(d) : "r"(v)); return d;
}

// order-preserving float<->uint for atomicMax/Min on signed floats
__device__ __forceinline__ unsigned enc_f(float f) {
    unsigned u = __float_as_uint(f);
    return (u & 0x80000000u) ? ~u : (u | 0x80000000u);
}
__device__ __forceinline__ float dec_f(unsigned u) {
    unsigned v = (u & 0x80000000u) ? (u & 0x7FFFFFFFu) : ~u;
    return __uint_as_float(v);
}
#define ENC_NEG_INF 0x007FFFFFu
#define ENC_POS_INF 0xFF800000u

// exact (non-FMA) squared distance, matching XLA f32: (dx*dx + dy*dy) + dz*dz
__device__ __forceinline__ float d2_exact(float dx, float dy, float dz) {
    return __fadd_rn(__fadd_rn(__fmul_rn(dx,dx), __fmul_rn(dy,dy)), __fmul_rn(dz,dz));
}

// ---------------- kernel 0: zero stats ----------------
__global__ void zero_stats() {
    int t = threadIdx.x;
    if (t < 64) { g_sum1[t]=0.f; g_sq1[t]=0.f; g_sum2[t]=0.f; g_sq2[t]=0.f; }
    if (t < 128){ g_sum3[t]=0.f; g_sq3[t]=0.f; }
}

// ---------------- kernel 1: furthest point sampling (r8, unchanged) ----------------
#define FPS_SMEM (3*N_*4 + NPOINT*4 + 2*64*4)
__global__ __launch_bounds__(1024, 1) void fps_kernel(const float* __restrict__ xyz,
                                                      float* __restrict__ newxyz) {
    extern __shared__ float sm[];
    float* xs = sm;
    float* ys = sm + N_;
    float* zs = sm + 2*N_;
    int*   picks = (int*)(sm + 3*N_);
    unsigned* sval = (unsigned*)(picks + NPOINT);  // [2][32]
    unsigned* sidx = sval + 64;                    // [2][32]

    const int b = blockIdx.x, tid = threadIdx.x;
    const int lane = tid & 31, wid = tid >> 5;
    const float* xb = xyz + (size_t)b * N_ * 3;

    for (int j = tid; j < 3*N_; j += 1024) {
        float v = xb[j];
        int p = j / 3, c = j - p*3;
        ((c == 0) ? xs : (c == 1) ? ys : zs)[p] = v;
    }
    if (tid == 0) picks[0] = 0;
    __syncthreads();

    float2 RX[4], RY[4], RZ[4];
    unsigned Du[8];
#pragma unroll
    for (int j = 0; j < 4; j++) {
        int p0 = tid + (2*j)*1024, p1 = p0 + 1024;
        RX[j] = make_float2(xs[p0], xs[p1]);
        RY[j] = make_float2(ys[p0], ys[p1]);
        RZ[j] = make_float2(zs[p0], zs[p1]);
        Du[2*j]   = __float_as_uint(1e10f);
        Du[2*j+1] = __float_as_uint(1e10f);
    }

    int last = 0;
    for (int it = 1; it < NPOINT; ++it) {
        float px = xs[last], py = ys[last], pz = zs[last];
        float2 nx2 = make_float2(-px, -px);
        float2 ny2 = make_float2(-py, -py);
        float2 nz2 = make_float2(-pz, -pz);

#pragma unroll
        for (int j = 0; j < 4; j++) {
            float2 dx = fadd2(RX[j], nx2);
            float2 dy = fadd2(RY[j], ny2);
            float2 dz = fadd2(RZ[j], nz2);
            float2 s  = fadd2(fadd2(fmul2(dx,dx), fmul2(dy,dy)), fmul2(dz,dz));
            Du[2*j]   = umin(Du[2*j],   __float_as_uint(s.x));
            Du[2*j+1] = umin(Du[2*j+1], __float_as_uint(s.y));
        }
        unsigned m01 = umax(Du[0], Du[1]), m23 = umax(Du[2], Du[3]);
        unsigned m45 = umax(Du[4], Du[5]), m67 = umax(Du[6], Du[7]);
        unsigned bv  = umax(umax(m01, m23), umax(m45, m67));

        unsigned wmax = redux_max_u32(bv);
        const int buf = (it & 1) << 5;
        if (lane == 0) sval[buf + wid] = wmax;
        __syncthreads();
        unsigned gm = redux_max_u32(sval[buf + lane]);   // global max value

        unsigned idxv = 0xFFFFFFFFu;
        if (wmax == gm) {                 // warp-uniform
            unsigned cand = 0xFFFFFFFFu;
            if (bv == gm) {
#pragma unroll
                for (int s = 7; s >= 0; --s)
                    if (Du[s] == gm) cand = (unsigned)(tid + (s << 10));
            }
            idxv = redux_min_u32(cand);
        }
        if (lane == 0) sidx[buf + wid] = idxv;
        __syncthreads();
        last = (int)redux_min_u32(sidx[buf + lane]);
        if (tid == 0) picks[it] = last;
    }
    __syncthreads();
    for (int s = tid; s < NPOINT; s += 1024) {
        int j = picks[s];
        float* o = newxyz + (size_t)(b*NPOINT + s)*3;
        o[0] = xs[j]; o[1] = ys[j]; o[2] = zs[j];
    }
}

// ---------------- kernel 2: ball query (warp-autonomous, unchanged) ----------------
__global__ __launch_bounds__(256) void ball_kernel(const float* __restrict__ xyz,
                                                   const float* __restrict__ nxyz) {
    __shared__ int sidx[8][32];
    const int lane = threadIdx.x & 31, w = threadIdx.x >> 5;
    const int g = blockIdx.x * 8 + w;           // global query id
    const int b = g >> 11;                      // 2048 queries per batch
    const float* qp = nxyz + (size_t)g * 3;
    const float qx = qp[0], qy = qp[1], qz = qp[2];
    const float R2f = (float)(0.4 * 0.4);
    const float* xb = xyz + (size_t)b * N_ * 3;

    int cnt = 0;
    for (int t0 = 0; t0 < N_; t0 += 32) {
        const int p = t0 + lane;
        const float* pp = xb + (size_t)p * 3;
        float x = __ldg(pp), y = __ldg(pp + 1), z = __ldg(pp + 2);
        float d2 = d2_exact(qx - x, qy - y, qz - z);
        bool ok = d2 < R2f;
        unsigned m = __ballot_sync(0xffffffffu, ok);
        if (m) {
            int pos = cnt + __popc(m & ((1u << lane) - 1u));
            if (ok && pos < 32) sidx[w][pos] = p;
            cnt += __popc(m);
            if (cnt >= 32) break;
        }
    }
    __syncwarp();
    int v = 0;
    if (cnt) {
        int first = sidx[w][0];
        v = (lane < cnt) ? sidx[w][lane] : first;
    }
    d_ball[((size_t)g << 5) + lane] = v;
}

// ================= GEMM micro-kernels (r12 anchor) =================

// ---------------- GEMM 1: feats(gathered 67) @ W1 -> out1T + stats ----------------
#define G1_SMEM ((67*132 + 67*64)*4)
__global__ __launch_bounds__(256, 4) void gemm1_kernel(const float* __restrict__ xyz,
                                                       const float* __restrict__ points,
                                                       const float* __restrict__ W1,
                                                       const float* __restrict__ nxyz) {
    extern __shared__ float sm[];
    float* As = sm;             // [67][132] k-major
    float* Bs = sm + 67*132;    // [67][64]
    __shared__ float ssum[64], ssq[64];

    const int tid = threadIdx.x;
    const int R0 = blockIdx.x * 128;
    if (tid < 64) { ssum[tid] = 0.f; ssq[tid] = 0.f; }
    for (int i = tid; i < 67*64; i += 256) Bs[i] = W1[i];

    const int wid = tid >> 5, lane = tid & 31;
    for (int rr = wid; rr < 128; rr += 8) {
        int row = R0 + rr;
        int b = row >> 16, rem = row & 65535, s = rem >> 5;
        int j = d_ball[row];
        const float* prow = points + ((size_t)(b*N_ + j)) * 64;
        As[(3 + lane)*132 + rr]  = prow[lane];
        As[(35 + lane)*132 + rr] = prow[lane + 32];
        if (lane < 3)
            As[lane*132 + rr] = xyz[(size_t)(b*N_ + j)*3 + lane]
                              - nxyz[(size_t)(b*NPOINT + s)*3 + lane];
    }
    __syncthreads();

    const int tc = tid & 15, tr = tid >> 4;
    float2 acc[4][4];   // [rowpair][col]
#pragma unroll
    for (int r = 0; r < 4; r++)
#pragma unroll
        for (int c = 0; c < 4; c++) acc[r][c] = make_float2(0.f, 0.f);

    for (int kk = 0; kk < 67; ++kk) {
        float4 a0 = *(const float4*)(As + kk*132 + tr*8);
        float4 a1 = *(const float4*)(As + kk*132 + tr*8 + 4);
        float2 ap[4] = { make_float2(a0.x,a0.y), make_float2(a0.z,a0.w),
                         make_float2(a1.x,a1.y), make_float2(a1.z,a1.w) };
        float4 b4 = *(const float4*)(Bs + kk*64 + tc*4);
        float2 bb[4] = { make_float2(b4.x,b4.x), make_float2(b4.y,b4.y),
                         make_float2(b4.z,b4.z), make_float2(b4.w,b4.w) };
#pragma unroll
        for (int r = 0; r < 4; r++)
#pragma unroll
            for (int c = 0; c < 4; c++)
                acc[r][c] = ffma2(ap[r], bb[c], acc[r][c]);
    }

    // epilogue: transposed store (column-major) + stats (shfl pre-combine)
    float cs[4], cq[4];
#pragma unroll
    for (int c = 0; c < 4; c++) {
        int col = tc*4 + c;
        float4 v0 = make_float4(acc[0][c].x, acc[0][c].y, acc[1][c].x, acc[1][c].y);
        float4 v1 = make_float4(acc[2][c].x, acc[2][c].y, acc[3][c].x, acc[3][c].y);
        *(float4*)(d_out1T + (size_t)col*ROWS_TOTAL + R0 + tr*8)     = v0;
        *(float4*)(d_out1T + (size_t)col*ROWS_TOTAL + R0 + tr*8 + 4) = v1;
        cs[c] = v0.x+v0.y+v0.z+v0.w + v1.x+v1.y+v1.z+v1.w;
        cq[c] = v0.x*v0.x+v0.y*v0.y+v0.z*v0.z+v0.w*v0.w
              + v1.x*v1.x+v1.y*v1.y+v1.z*v1.z+v1.w*v1.w;
    }
#pragma unroll
    for (int c = 0; c < 4; c++) {
        cs[c] += __shfl_xor_sync(0xffffffffu, cs[c], 16);
        cq[c] += __shfl_xor_sync(0xffffffffu, cq[c], 16);
    }
    if (!(tr & 1)) {
#pragma unroll
        for (int c = 0; c < 4; c++) {
            atomicAdd(&ssum[tc*4+c], cs[c]);
            atomicAdd(&ssq [tc*4+c], cq[c]);
        }
    }
    __syncthreads();
    if (tid < 64) { atomicAdd(&g_sum1[tid], ssum[tid]); atomicAdd(&g_sq1[tid], ssq[tid]); }
}

// ---------------- GEMM 2: relu(bn1(out1T)) @ W2 -> out2T + stats ----------------
#define G2_SMEM ((64*132 + 64*64)*4)
__global__ __launch_bounds__(256, 4) void gemm2_kernel(const float* __restrict__ W2) {
    extern __shared__ float sm[];
    float* As = sm;             // [64][132]
    float* Bs = sm + 64*132;    // [64][64]
    __shared__ float ssum[64], ssq[64];

    const int tid = threadIdx.x;
    const int R0 = blockIdx.x * 128;
    if (tid < 64) { ssum[tid] = 0.f; ssq[tid] = 0.f; }
    for (int i = tid; i < 64*64; i += 256) Bs[i] = W2[i];

    const int wid = tid >> 5, lane = tid & 31;
    // gather: warps 0-3 rows 0-127 / c 0-31, warps 4-7 same rows / c 32-63
    {
        const int rbase = (wid & 3)*32 + lane;       // 0..127
        const int c0 = (wid >> 2)*32;
        const float* src = d_out1T + R0 + rbase;
#pragma unroll 4
        for (int cc = 0; cc < 32; cc++) {
            int c = c0 + cc;
            float v = __ldg(src + (size_t)c*ROWS_TOTAL);
            As[c*132 + rbase] = fmaxf(0.f, fmaf(v, __ldg(&g_scale1[c]), __ldg(&g_shift1[c])));
        }
    }
    __syncthreads();

    const int tc = tid & 15, tr = tid >> 4;
    float2 acc[4][4];
#pragma unroll
    for (int r = 0; r < 4; r++)
#pragma unroll
        for (int c = 0; c < 4; c++) acc[r][c] = make_float2(0.f, 0.f);

    for (int kk = 0; kk < 64; ++kk) {
        float4 a0 = *(const float4*)(As + kk*132 + tr*8);
        float4 a1 = *(const float4*)(As + kk*132 + tr*8 + 4);
        float2 ap[4] = { make_float2(a0.x,a0.y), make_float2(a0.z,a0.w),
                         make_float2(a1.x,a1.y), make_float2(a1.z,a1.w) };
        float4 b4 = *(const float4*)(Bs + kk*64 + tc*4);
        float2 bb[4] = { make_float2(b4.x,b4.x), make_float2(b4.y,b4.y),
                         make_float2(b4.z,b4.z), make_float2(b4.w,b4.w) };
#pragma unroll
        for (int r = 0; r < 4; r++)
#pragma unroll
            for (int c = 0; c < 4; c++)
                acc[r][c] = ffma2(ap[r], bb[c], acc[r][c]);
    }

    float cs[4], cq[4];
#pragma unroll
    for (int c = 0; c < 4; c++) {
        int col = tc*4 + c;
        float4 v0 = make_float4(acc[0][c].x, acc[0][c].y, acc[1][c].x, acc[1][c].y);
        float4 v1 = make_float4(acc[2][c].x, acc[2][c].y, acc[3][c].x, acc[3][c].y);
        *(float4*)(d_out2T + (size_t)col*ROWS_TOTAL + R0 + tr*8)     = v0;
        *(float4*)(d_out2T + (size_t)col*ROWS_TOTAL + R0 + tr*8 + 4) = v1;
        cs[c] = v0.x+v0.y+v0.z+v0.w + v1.x+v1.y+v1.z+v1.w;
        cq[c] = v0.x*v0.x+v0.y*v0.y+v0.z*v0.z+v0.w*v0.w
              + v1.x*v1.x+v1.y*v1.y+v1.z*v1.z+v1.w*v1.w;
    }
#pragma unroll
    for (int c = 0; c < 4; c++) {
        cs[c] += __shfl_xor_sync(0xffffffffu, cs[c], 16);
        cq[c] += __shfl_xor_sync(0xffffffffu, cq[c], 16);
    }
    if (!(tr & 1)) {
#pragma unroll
        for (int c = 0; c < 4; c++) {
            atomicAdd(&ssum[tc*4+c], cs[c]);
            atomicAdd(&ssq [tc*4+c], cq[c]);
        }
    }
    __syncthreads();
    if (tid < 64) { atomicAdd(&g_sum2[tid], ssum[tid]); atomicAdd(&g_sq2[tid], ssq[tid]); }
}

// ---------------- GEMM 3 (column-split): relu(bn2(out2T)) @ W3[:,half] ----------------
// grid (4096, 2): blockIdx.y = column half. 50 KB smem -> 4 blocks/SM, and the
// inner loop matches the proven gemm1/2 shape (16 FFMA2 : 3 LDS.128 per k).
#define G3_SMEM ((64*132 + 64*64)*4)
__global__ __launch_bounds__(256, 4) void gemm3_kernel(const float* __restrict__ W3) {
    extern __shared__ float sm[];
    float* As = sm;            // [64][132] k-major
    float* Bs = sm + 64*132;   // [64][64] (this half's columns)
    __shared__ unsigned smax[256], smin[256];   // [4 groups][64 cols]
    __shared__ float ssum[64], ssq[64];

    const int tid = threadIdx.x;
    const int R0 = blockIdx.x * 128;
    const int half = blockIdx.y;            // 0 or 1
    const int cbase = half * 64;
    for (int i = tid; i < 256; i += 256) { smax[i] = ENC_NEG_INF; smin[i] = ENC_POS_INF; }
    if (tid < 64) { ssum[tid] = 0.f; ssq[tid] = 0.f; }
    for (int i = tid; i < 64*64; i += 256) {
        int k = i >> 6, c = i & 63;
        Bs[i] = W3[k*128 + cbase + c];
    }

    const int wid = tid >> 5, lane = tid & 31;
    // gather: warps 0-3 rows / c 0-31, warps 4-7 same rows / c 32-63
    {
        const int rbase = (wid & 3)*32 + lane;       // 0..127
        const int c0 = (wid >> 2)*32;
        const float* src = d_out2T + R0 + rbase;
#pragma unroll 4
        for (int cc = 0; cc < 32; cc++) {
            int c = c0 + cc;
            float v = __ldg(src + (size_t)c*ROWS_TOTAL);
            As[c*132 + rbase] = fmaxf(0.f, fmaf(v, __ldg(&g_scale2[c]), __ldg(&g_shift2[c])));
        }
    }
    __syncthreads();

    const int tc = tid & 15, tr = tid >> 4;
    float2 acc[4][4];   // [rowpair][col]
#pragma unroll
    for (int r = 0; r < 4; r++)
#pragma unroll
        for (int c = 0; c < 4; c++) acc[r][c] = make_float2(0.f, 0.f);

    for (int kk = 0; kk < 64; ++kk) {
        float4 a0 = *(const float4*)(As + kk*132 + tr*8);
        float4 a1 = *(const float4*)(As + kk*132 + tr*8 + 4);
        float2 ap[4] = { make_float2(a0.x,a0.y), make_float2(a0.z,a0.w),
                         make_float2(a1.x,a1.y), make_float2(a1.z,a1.w) };
        float4 b4 = *(const float4*)(Bs + kk*64 + tc*4);
        float2 bb[4] = { make_float2(b4.x,b4.x), make_float2(b4.y,b4.y),
                         make_float2(b4.z,b4.z), make_float2(b4.w,b4.w) };
#pragma unroll
        for (int r = 0; r < 4; r++)
#pragma unroll
            for (int c = 0; c < 4; c++)
                acc[r][c] = ffma2(ap[r], bb[c], acc[r][c]);
    }

    const int gl = tr >> 2;   // 8 rows of this thread lie in local group tr>>2
#pragma unroll
    for (int c = 0; c < 4; c++) {
        int col = tc*4 + c;     // local column 0..63
        float mx, mn, su, sq;
        {
            float v0 = acc[0][c].x, v1 = acc[0][c].y;
            mx = fmaxf(v0, v1); mn = fminf(v0, v1);
            su = v0 + v1; sq = v0*v0 + v1*v1;
        }
#pragma unroll
        for (int r = 1; r < 4; r++) {
            float v0 = acc[r][c].x, v1 = acc[r][c].y;
            mx = fmaxf(mx, fmaxf(v0, v1));
            mn = fminf(mn, fminf(v0, v1));
            su += v0 + v1; sq += v0*v0 + v1*v1;
        }
        // shfl pre-combine: tid^16 = tr^1 -> same warp, same col, same gl
        mx = fmaxf(mx, __shfl_xor_sync(0xffffffffu, mx, 16));
        mn = fminf(mn, __shfl_xor_sync(0xffffffffu, mn, 16));
        su += __shfl_xor_sync(0xffffffffu, su, 16);
        sq += __shfl_xor_sync(0xffffffffu, sq, 16);
        if (!(tr & 1)) {
            atomicMax(&smax[gl*64 + col], enc_f(mx));
            atomicMin(&smin[gl*64 + col], enc_f(mn));
            atomicAdd(&ssum[col], su);
            atomicAdd(&ssq [col], sq);
        }
    }
    __syncthreads();
    // write this half's 64-col slices of the 4 groups
    for (int i = tid; i < 256; i += 256) {
        int g = i >> 6, c = i & 63;
        size_t o = ((size_t)(blockIdx.x*4 + g))*128 + cbase + c;
        d_gmax[o] = dec_f(smax[i]);
        d_gmin[o] = dec_f(smin[i]);
    }
    if (tid < 64) {
        atomicAdd(&g_sum3[cbase + tid], ssum[tid]);
        atomicAdd(&g_sq3 [cbase + tid], ssq[tid]);
    }
}

// ---------------- prep: stats -> (scale, shift) ----------------
__global__ void prep_kernel(const float* __restrict__ g, const float* __restrict__ bt,
                            int layer) {
    int c = threadIdx.x;
    int C = (layer == 2) ? 128 : 64;
    if (c >= C) return;
    const float* sums = (layer==0) ? g_sum1 : (layer==1) ? g_sum2 : g_sum3;
    const float* sqs  = (layer==0) ? g_sq1  : (layer==1) ? g_sq2  : g_sq3;
    float* scp = (layer==0) ? g_scale1 : (layer==1) ? g_scale2 : g_scale3;
    float* shp = (layer==0) ? g_shift1 : (layer==1) ? g_shift2 : g_shift3;
    const float inv = 1.f / (float)ROWS_TOTAL;
    float m = sums[c] * inv;
    float v = fmaxf(sqs[c] * inv - m*m, 0.f);
    float s = g[c] * rsqrtf(v + 1e-5f);
    scp[c] = s;
    shp[c] = bt[c] - m * s;
}

// ---------------- finalize: pick max/min by BN sign, apply BN+relu ----------------
__global__ void finalize_kernel(float* __restrict__ outp) {
    int i = blockIdx.x * 256 + threadIdx.x;   // [group][channel] linear
    int c = i & 127;
    float s = g_scale3[c];
    float v = (s >= 0.f) ? d_gmax[i] : d_gmin[i];
    outp[i] = fmaxf(0.f, fmaf(s, v, g_shift3[c]));
}

// ---------------- launch ----------------
extern "C" void kernel_launch(void* const* d_in, const int* in_sizes, int n_in,
                              void* d_out, int out_size) {
    const float* xyz    = (const float*)d_in[0];
    const float* points = (const float*)d_in[1];
    const float* W1 = (const float*)d_in[2];
    const float* g1 = (const float*)d_in[3];
    const float* b1 = (const float*)d_in[4];
    const float* W2 = (const float*)d_in[5];
    const float* g2 = (const float*)d_in[6];
    const float* b2 = (const float*)d_in[7];
    const float* W3 = (const float*)d_in[8];
    const float* g3 = (const float*)d_in[9];
    const float* b3 = (const float*)d_in[10];

    float* out    = (float*)d_out;
    float* newxyz = out;                       // [8][2048][3]
    float* newpts = out + (size_t)B_*NPOINT*3; // [8][2048][128]

    cudaFuncSetAttribute(fps_kernel,   cudaFuncAttributeMaxDynamicSharedMemorySize, FPS_SMEM);
    cudaFuncSetAttribute(gemm1_kernel, cudaFuncAttributeMaxDynamicSharedMemorySize, G1_SMEM);
    cudaFuncSetAttribute(gemm2_kernel, cudaFuncAttributeMaxDynamicSharedMemorySize, G2_SMEM);
    cudaFuncSetAttribute(gemm3_kernel, cudaFuncAttributeMaxDynamicSharedMemorySize, G3_SMEM);
    cudaFuncSetAttribute(fps_kernel,   cudaFuncAttributePreferredSharedMemoryCarveout, 100);

    zero_stats<<<1, 128>>>();
    fps_kernel<<<B_, 1024, FPS_SMEM>>>(xyz, newxyz);
    ball_kernel<<<NGROUP/8, 256>>>(xyz, newxyz);
    gemm1_kernel<<<ROWS_TOTAL/128, 256, G1_SMEM>>>(xyz, points, W1, newxyz);
    prep_kernel<<<1, 128>>>(g1, b1, 0);
    gemm2_kernel<<<ROWS_TOTAL/128, 256, G2_SMEM>>>(W2);
    prep_kernel<<<1, 128>>>(g2, b2, 1);
    dim3 g3grid(ROWS_TOTAL/128, 2);
    gemm3_kernel<<<g3grid, 256, G3_SMEM>>>(W3);
    prep_kernel<<<1, 128>>>(g3, b3, 2);
    finalize_kernel<<<(B_*NPOINT*128)/256, 256>>>(newpts);
}